// round 2
// baseline (speedup 1.0000x reference)
#include <cuda_runtime.h>
#include <math.h>
#include <stdint.h>

#define BB 8
#define LL 512
#define DD 512
#define HH 8
#define DH 64
#define BL 4096                 // B*L rows
#define NELEM 2097152           // B*L*D

// ---------------- scratch (static device globals; no allocation) ----------------
__device__ float d_xn[BL * DD];            // LN output / GEMM input
__device__ float d_qkv[BL * 3 * DD];       // QKV projection
__device__ float d_scores[(size_t)BB * HH * LL * LL]; // attention scores (64 MB)
__device__ float d_attno[BL * DD];         // attention output (head-merged)
__device__ float d_x2[BL * DD];            // x after attention residual
__device__ float d_ffh[BL * 4 * DD];       // FFN hidden
__device__ float d_xout[BL * DD];          // expert output
__device__ float d_sum[BL * DD];           // sum of primary expert outputs
__device__ float d_meaneo[4 * DD];         // per-primary-expert column sums
__device__ float d_stats[4];               // [0]=sum d, [1]=sum d^2, [2]=rate

// ---------------- helpers ----------------
__device__ __forceinline__ float warp_sum(float v) {
#pragma unroll
    for (int o = 16; o > 0; o >>= 1) v += __shfl_xor_sync(0xffffffffu, v, o);
    return v;
}
__device__ __forceinline__ float warp_max(float v) {
#pragma unroll
    for (int o = 16; o > 0; o >>= 1) v = fmaxf(v, __shfl_xor_sync(0xffffffffu, v, o));
    return v;
}
__device__ __forceinline__ float gelu_tanh(float v) {
    float c = 0.7978845608028654f * (v + 0.044715f * v * v * v);
    return 0.5f * v * (1.0f + tanhf(c));
}

// ---------------- LayerNorm: one block per row (D=512, 128 thr x float4) ----------------
__global__ void ln_kernel(const float* __restrict__ x, const float* __restrict__ sc,
                          const float* __restrict__ bi, float* __restrict__ y)
{
    __shared__ float sm[8];
    int row = blockIdx.x;
    int t = threadIdx.x;
    float4 v = reinterpret_cast<const float4*>(x + (size_t)row * DD)[t];
    float s = v.x + v.y + v.z + v.w;
    float q = v.x * v.x + v.y * v.y + v.z * v.z + v.w * v.w;
    s = warp_sum(s); q = warp_sum(q);
    if ((t & 31) == 0) { sm[t >> 5] = s; sm[4 + (t >> 5)] = q; }
    __syncthreads();
    float S = sm[0] + sm[1] + sm[2] + sm[3];
    float Q = sm[4] + sm[5] + sm[6] + sm[7];
    float mean = S * (1.0f / DD);
    float var  = Q * (1.0f / DD) - mean * mean;
    float inv  = rsqrtf(var + 1e-5f);
    float4 scv = reinterpret_cast<const float4*>(sc)[t];
    float4 biv = reinterpret_cast<const float4*>(bi)[t];
    float4 o;
    o.x = (v.x - mean) * inv * scv.x + biv.x;
    o.y = (v.y - mean) * inv * scv.y + biv.y;
    o.z = (v.z - mean) * inv * scv.z + biv.z;
    o.w = (v.w - mean) * inv * scv.w + biv.w;
    reinterpret_cast<float4*>(y + (size_t)row * DD)[t] = o;
}

// ---------------- SGEMM: 128x128 block tile, BK=16, 8x8/thread, 256 threads ----------------
// EPI: 0 = +bias, 1 = +bias then gelu, 2 = +bias then +residual
template<int EPI>
__global__ void __launch_bounds__(256)
sgemm_kernel(const float* __restrict__ A, const float* __restrict__ B,
             const float* __restrict__ bias, const float* __restrict__ res,
             float* __restrict__ C, int M, int N, int K)
{
    const int BM = 128, BN = 128, BK = 16, TM = 8, TN = 8;
    __shared__ float As[BK][BM];
    __shared__ float Bs[BK][BN];
    int tid = threadIdx.x;
    int tx = tid & 15, ty = tid >> 4;
    int bm = blockIdx.y * BM, bn = blockIdx.x * BN;
    const float* Ablk = A + (size_t)bm * K;
    const float* Bblk = B + bn;
    float acc[TM][TN];
#pragma unroll
    for (int i = 0; i < TM; i++)
#pragma unroll
        for (int j = 0; j < TN; j++) acc[i][j] = 0.f;

    for (int k0 = 0; k0 < K; k0 += BK) {
#pragma unroll
        for (int t = 0; t < 2; t++) {                 // A: 128x16 = 512 float4
            int idx = tid + t * 256;
            int row = idx >> 2;
            int col = (idx & 3) << 2;
            float4 v = *reinterpret_cast<const float4*>(Ablk + (size_t)row * K + k0 + col);
            As[col + 0][row] = v.x; As[col + 1][row] = v.y;
            As[col + 2][row] = v.z; As[col + 3][row] = v.w;
        }
#pragma unroll
        for (int t = 0; t < 2; t++) {                 // B: 16x128 = 512 float4
            int idx = tid + t * 256;
            int row = idx >> 5;
            int col = (idx & 31) << 2;
            *reinterpret_cast<float4*>(&Bs[row][col]) =
                *reinterpret_cast<const float4*>(Bblk + (size_t)(k0 + row) * N + col);
        }
        __syncthreads();
#pragma unroll
        for (int kk = 0; kk < BK; kk++) {
            float ra[TM], rb[TN];
            *reinterpret_cast<float4*>(&ra[0]) = *reinterpret_cast<const float4*>(&As[kk][ty * TM]);
            *reinterpret_cast<float4*>(&ra[4]) = *reinterpret_cast<const float4*>(&As[kk][ty * TM + 4]);
            *reinterpret_cast<float4*>(&rb[0]) = *reinterpret_cast<const float4*>(&Bs[kk][tx * TN]);
            *reinterpret_cast<float4*>(&rb[4]) = *reinterpret_cast<const float4*>(&Bs[kk][tx * TN + 4]);
#pragma unroll
            for (int i = 0; i < TM; i++)
#pragma unroll
                for (int j = 0; j < TN; j++) acc[i][j] = fmaf(ra[i], rb[j], acc[i][j]);
        }
        __syncthreads();
    }
#pragma unroll
    for (int i = 0; i < TM; i++) {
        int r = bm + ty * TM + i;
#pragma unroll
        for (int j = 0; j < TN; j++) {
            int c = bn + tx * TN + j;
            float v = acc[i][j] + bias[c];
            if (EPI == 1) v = gelu_tanh(v);
            if (EPI == 2) v += res[(size_t)r * N + c];
            C[(size_t)r * N + c] = v;
        }
    }
}

// ---------------- attention scores: 64x64 tile per block, K=dh=64 ----------------
__global__ void __launch_bounds__(256)
attn_scores_kernel(const float* __restrict__ qkv, float* __restrict__ scores)
{
    int bh = blockIdx.z;
    int b = bh >> 3, h = bh & 7;
    int i0 = blockIdx.y * 64, j0 = blockIdx.x * 64;
    __shared__ float Qs[64][65];
    __shared__ float Ks[64][65];
    const float* qbase = qkv + ((size_t)b * LL + i0) * (3 * DD) + h * DH;
    const float* kbase = qkv + ((size_t)b * LL + j0) * (3 * DD) + DD + h * DH;
    int tid = threadIdx.x;
#pragma unroll
    for (int t = 0; t < 4; t++) {
        int idx = tid + t * 256;
        int r = idx >> 4;
        int c = (idx & 15) << 2;
        float4 q = *reinterpret_cast<const float4*>(qbase + (size_t)r * (3 * DD) + c);
        float4 k = *reinterpret_cast<const float4*>(kbase + (size_t)r * (3 * DD) + c);
        Qs[r][c] = q.x; Qs[r][c + 1] = q.y; Qs[r][c + 2] = q.z; Qs[r][c + 3] = q.w;
        Ks[r][c] = k.x; Ks[r][c + 1] = k.y; Ks[r][c + 2] = k.z; Ks[r][c + 3] = k.w;
    }
    __syncthreads();
    int tx = tid & 15, ty = tid >> 4;
    float acc[4][4] = {};
#pragma unroll
    for (int d = 0; d < 64; d++) {
        float rq[4], rk[4];
#pragma unroll
        for (int i = 0; i < 4; i++) rq[i] = Qs[ty * 4 + i][d];
#pragma unroll
        for (int j = 0; j < 4; j++) rk[j] = Ks[tx * 4 + j][d];
#pragma unroll
        for (int i = 0; i < 4; i++)
#pragma unroll
            for (int j = 0; j < 4; j++) acc[i][j] = fmaf(rq[i], rk[j], acc[i][j]);
    }
    float* out = scores + ((size_t)bh * LL + i0) * LL + j0;
#pragma unroll
    for (int i = 0; i < 4; i++)
#pragma unroll
        for (int j = 0; j < 4; j++)
            out[(size_t)(ty * 4 + i) * LL + tx * 4 + j] = acc[i][j] * 0.125f;
}

// ---------------- row softmax over 512 ----------------
__global__ void softmax_kernel(float* __restrict__ scores)
{
    __shared__ float sm[8];
    size_t row = blockIdx.x;
    int t = threadIdx.x;  // 128
    float4* p = reinterpret_cast<float4*>(scores + row * (size_t)LL);
    float4 v = p[t];
    float m = fmaxf(fmaxf(v.x, v.y), fmaxf(v.z, v.w));
    m = warp_max(m);
    if ((t & 31) == 0) sm[t >> 5] = m;
    __syncthreads();
    m = fmaxf(fmaxf(sm[0], sm[1]), fmaxf(sm[2], sm[3]));
    v.x = __expf(v.x - m); v.y = __expf(v.y - m);
    v.z = __expf(v.z - m); v.w = __expf(v.w - m);
    float s = v.x + v.y + v.z + v.w;
    s = warp_sum(s);
    if ((t & 31) == 0) sm[4 + (t >> 5)] = s;
    __syncthreads();
    s = sm[4] + sm[5] + sm[6] + sm[7];
    float inv = __frcp_rn(s);
    v.x *= inv; v.y *= inv; v.z *= inv; v.w *= inv;
    p[t] = v;
}

// ---------------- attn @ V: 64-row tile x dh=64, K=512 ----------------
__global__ void __launch_bounds__(256)
attn_av_kernel(const float* __restrict__ scores, const float* __restrict__ qkv,
               float* __restrict__ o)
{
    int bh = blockIdx.y;
    int b = bh >> 3, h = bh & 7;
    int i0 = blockIdx.x * 64;
    __shared__ float Ss[64][65];
    __shared__ float Vs[64][65];
    int tid = threadIdx.x;
    int tx = tid & 15, ty = tid >> 4;
    float acc[4][4] = {};
    for (int k0 = 0; k0 < LL; k0 += 64) {
#pragma unroll
        for (int t = 0; t < 4; t++) {
            int idx = tid + t * 256;
            int r = idx >> 4;
            int c = (idx & 15) << 2;
            float4 s = *reinterpret_cast<const float4*>(
                scores + ((size_t)bh * LL + i0 + r) * LL + k0 + c);
            float4 vv = *reinterpret_cast<const float4*>(
                qkv + ((size_t)b * LL + k0 + r) * (3 * DD) + 2 * DD + h * DH + c);
            Ss[r][c] = s.x; Ss[r][c + 1] = s.y; Ss[r][c + 2] = s.z; Ss[r][c + 3] = s.w;
            Vs[r][c] = vv.x; Vs[r][c + 1] = vv.y; Vs[r][c + 2] = vv.z; Vs[r][c + 3] = vv.w;
        }
        __syncthreads();
#pragma unroll
        for (int kk = 0; kk < 64; kk++) {
            float rs[4], rv[4];
#pragma unroll
            for (int i = 0; i < 4; i++) rs[i] = Ss[ty * 4 + i][kk];
#pragma unroll
            for (int j = 0; j < 4; j++) rv[j] = Vs[kk][tx * 4 + j];
#pragma unroll
            for (int i = 0; i < 4; i++)
#pragma unroll
                for (int j = 0; j < 4; j++) acc[i][j] = fmaf(rs[i], rv[j], acc[i][j]);
        }
        __syncthreads();
    }
#pragma unroll
    for (int i = 0; i < 4; i++)
#pragma unroll
        for (int j = 0; j < 4; j++)
            o[((size_t)b * LL + i0 + ty * 4 + i) * DD + h * DH + tx * 4 + j] = acc[i][j];
}

// ---------------- accumulate expert output into sum; column sums into meaneo ----------------
__global__ void accum_colmean_kernel(const float* __restrict__ xout, float* __restrict__ sum,
                                     float* __restrict__ meaneo, int first)
{
    // grid 32 blocks (128 rows each) x 512 threads (one per column)
    int t = threadIdx.x;
    int r0 = blockIdx.x * 128;
    float local = 0.f;
    for (int r = r0; r < r0 + 128; r++) {
        size_t idx = (size_t)r * DD + t;
        float v = xout[idx];
        local += v;
        if (first) sum[idx] = v; else sum[idx] += v;
    }
    atomicAdd(&meaneo[t], local);
}

// ---------------- sum / sum^2 of (x - recon) ----------------
__global__ void uvar_kernel(const float* __restrict__ x, const float* __restrict__ sum,
                            float* __restrict__ stats)
{
    __shared__ float sm[16];
    float s1 = 0.f, s2 = 0.f;
    for (size_t i = (size_t)blockIdx.x * blockDim.x + threadIdx.x; i < NELEM;
         i += (size_t)gridDim.x * blockDim.x) {
        float d = x[i] - 0.25f * sum[i];
        s1 += d; s2 += d * d;
    }
    s1 = warp_sum(s1); s2 = warp_sum(s2);
    int w = threadIdx.x >> 5;
    if ((threadIdx.x & 31) == 0) { sm[w] = s1; sm[8 + w] = s2; }
    __syncthreads();
    if (threadIdx.x == 0) {
        float a = 0.f, b = 0.f;
        for (int i = 0; i < 8; i++) { a += sm[i]; b += sm[8 + i]; }
        atomicAdd(&stats[0], a);
        atomicAdd(&stats[1], b);
    }
}

// ---------------- gram / ortho / uvar / rate ----------------
__global__ void finalize_kernel(const float* __restrict__ meaneo, float* __restrict__ stats)
{
    __shared__ float sd[16];
    int t = threadIdx.x;  // 256
    if (t < 16) sd[t] = 0.f;
    __syncthreads();
    float l[4][4] = {};
    for (int c = t; c < DD; c += 256) {
        float v[4];
#pragma unroll
        for (int i = 0; i < 4; i++) v[i] = meaneo[i * DD + c];
#pragma unroll
        for (int i = 0; i < 4; i++)
#pragma unroll
            for (int j = i; j < 4; j++) l[i][j] += v[i] * v[j];
    }
#pragma unroll
    for (int i = 0; i < 4; i++)
#pragma unroll
        for (int j = i; j < 4; j++) atomicAdd(&sd[i * 4 + j], l[i][j]);
    __syncthreads();
    if (t == 0) {
        float nrm[4];
        for (int i = 0; i < 4; i++) nrm[i] = sqrtf(sd[i * 4 + i]);
        float off = 0.f;
        for (int i = 0; i < 4; i++)
            for (int j = 0; j < 4; j++) {
                float dot = (i <= j) ? sd[i * 4 + j] : sd[j * 4 + i];
                float g = dot / (nrm[i] * nrm[j]);
                float dlt = g - (i == j ? 1.0f : 0.0f);
                off += dlt * dlt;
            }
        float ortho = 1.0f - off / 16.0f;
        float S1 = stats[0], S2 = stats[1];
        const float N = (float)NELEM;
        float uvar = (S2 - S1 * S1 / N) / (N - 1.0f);
        float sat = ortho * uvar;
        stats[2] = (sat > 0.01f) ? 0.01f : 0.0f;
    }
}

// ---------------- final combine: (sum_prim + rate * ghost0) / 6 ----------------
__global__ void combine_kernel(const float* __restrict__ sum, const float* __restrict__ ghost,
                               const float* __restrict__ stats, float* __restrict__ out)
{
    float rate = stats[2];
    const float inv6 = 1.0f / 6.0f;
    size_t stride = (size_t)gridDim.x * blockDim.x;
    for (size_t i = (size_t)blockIdx.x * blockDim.x + threadIdx.x; i < NELEM / 4; i += stride) {
        float4 s = reinterpret_cast<const float4*>(sum)[i];
        float4 g = reinterpret_cast<const float4*>(ghost)[i];
        float4 o;
        o.x = (s.x + rate * g.x) * inv6;
        o.y = (s.y + rate * g.y) * inv6;
        o.z = (s.z + rate * g.z) * inv6;
        o.w = (s.w + rate * g.w) * inv6;
        reinterpret_cast<float4*>(out)[i] = o;
    }
}

// ---------------- orchestration ----------------
struct ExpertW {
    const float *ln1_s, *ln1_b, *wqkv, *bqkv, *wo, *bo, *ln2_s, *ln2_b, *w1, *b1, *w2, *b2;
};

static void run_expert(const float* x, const ExpertW& w,
                       float* xn, float* qkv, float* scores, float* attno,
                       float* x2, float* ffh, float* xout)
{
    ln_kernel<<<BL, 128>>>(x, w.ln1_s, w.ln1_b, xn);
    sgemm_kernel<0><<<dim3(3 * DD / 128, BL / 128), 256>>>(xn, w.wqkv, w.bqkv, nullptr, qkv, BL, 3 * DD, DD);
    attn_scores_kernel<<<dim3(LL / 64, LL / 64, BB * HH), 256>>>(qkv, scores);
    softmax_kernel<<<BB * HH * LL, 128>>>(scores);
    attn_av_kernel<<<dim3(LL / 64, BB * HH), 256>>>(scores, qkv, attno);
    sgemm_kernel<2><<<dim3(DD / 128, BL / 128), 256>>>(attno, w.wo, w.bo, x, x2, BL, DD, DD);
    ln_kernel<<<BL, 128>>>(x2, w.ln2_s, w.ln2_b, xn);
    sgemm_kernel<1><<<dim3(4 * DD / 128, BL / 128), 256>>>(xn, w.w1, w.b1, nullptr, ffh, BL, 4 * DD, DD);
    sgemm_kernel<2><<<dim3(DD / 128, BL / 128), 256>>>(ffh, w.w2, w.b2, x2, xout, BL, DD, 4 * DD);
}

extern "C" void kernel_launch(void* const* d_in, const int* in_sizes, int n_in,
                              void* d_out, int out_size)
{
    const float* x = (const float*)d_in[0];
    // primary params: d_in[2..13], ghost params: d_in[14..25]
    const float* p[12];
    const float* g[12];
    for (int i = 0; i < 12; i++) p[i] = (const float*)d_in[2 + i];
    for (int i = 0; i < 12; i++) g[i] = (const float*)d_in[14 + i];

    float *xn, *qkv, *scores, *attno, *x2, *ffh, *xout, *sum, *meaneo, *stats;
    cudaGetSymbolAddress((void**)&xn, d_xn);
    cudaGetSymbolAddress((void**)&qkv, d_qkv);
    cudaGetSymbolAddress((void**)&scores, d_scores);
    cudaGetSymbolAddress((void**)&attno, d_attno);
    cudaGetSymbolAddress((void**)&x2, d_x2);
    cudaGetSymbolAddress((void**)&ffh, d_ffh);
    cudaGetSymbolAddress((void**)&xout, d_xout);
    cudaGetSymbolAddress((void**)&sum, d_sum);
    cudaGetSymbolAddress((void**)&meaneo, d_meaneo);
    cudaGetSymbolAddress((void**)&stats, d_stats);

    cudaMemsetAsync(meaneo, 0, 4 * DD * sizeof(float));
    cudaMemsetAsync(stats, 0, 4 * sizeof(float));

    // per-expert weight strides within the stacked primary arrays (n=4)
    const size_t str[12] = { DD, DD, (size_t)DD * 3 * DD, 3 * DD, (size_t)DD * DD, DD,
                             DD, DD, (size_t)DD * 4 * DD, 4 * DD, (size_t)4 * DD * DD, DD };

    for (int e = 0; e < 4; e++) {
        ExpertW w;
        const float** f = (const float**)&w;
        for (int i = 0; i < 12; i++) f[i] = p[i] + (size_t)e * str[i];
        run_expert(x, w, xn, qkv, scores, attno, x2, ffh, xout);
        accum_colmean_kernel<<<32, 512>>>(xout, sum, meaneo + e * DD, e == 0);
    }

    // saturation statistics
    uvar_kernel<<<512, 256>>>(x, sum, stats);
    finalize_kernel<<<1, 256>>>(meaneo, stats);

    // ghost expert 0 (ghost 1 has rate 0 always -> skipped)
    {
        ExpertW w;
        const float** f = (const float**)&w;
        for (int i = 0; i < 12; i++) f[i] = g[i];   // index 0 of ghost stack
        run_expert(x, w, xn, qkv, scores, attno, x2, ffh, xout);
    }

    combine_kernel<<<1024, 256>>>(sum, xout, stats, (float*)d_out);
}

// round 3
// speedup vs baseline: 2.4664x; 2.4664x over previous
#include <cuda_runtime.h>
#include <math.h>
#include <stdint.h>

#define BB 8
#define LL 512
#define DD 512
#define HH 8
#define DH 64
#define BL 4096                 // B*L rows
#define NELEM 2097152           // B*L*D

// ---------------- scratch (static device globals; no allocation) ----------------
__device__ float d_xn[BL * DD];            // LN output / GEMM input
__device__ float d_qkv[BL * 3 * DD];       // QKV projection
__device__ float d_scores[(size_t)BB * HH * LL * LL]; // attention scores (64 MB)
__device__ float d_attno[BL * DD];         // attention output (head-merged)
__device__ float d_x2[BL * DD];            // x after attention residual
__device__ float d_ffh[BL * 4 * DD];       // FFN hidden
__device__ float d_xout[BL * DD];          // expert output
__device__ float d_sum[BL * DD];           // sum of primary expert outputs
__device__ float d_meaneo[4 * DD];         // per-primary-expert column sums
__device__ float d_stats[4];               // [0]=sum d, [1]=sum d^2, [2]=rate

// ---------------- helpers ----------------
__device__ __forceinline__ float warp_sum(float v) {
#pragma unroll
    for (int o = 16; o > 0; o >>= 1) v += __shfl_xor_sync(0xffffffffu, v, o);
    return v;
}
__device__ __forceinline__ float warp_max(float v) {
#pragma unroll
    for (int o = 16; o > 0; o >>= 1) v = fmaxf(v, __shfl_xor_sync(0xffffffffu, v, o));
    return v;
}
__device__ __forceinline__ float gelu_tanh(float v) {
    float c = 0.7978845608028654f * (v + 0.044715f * v * v * v);
    return 0.5f * v * (1.0f + tanhf(c));
}
__device__ __forceinline__ float to_tf32(float x) {
    float r;
    asm("cvt.rna.tf32.f32 %0, %1;" : "=f"(r) : "f"(x));
    return r;
}
__device__ __forceinline__ uint32_t f2u(float x) { return __float_as_uint(x); }

// one m16n8k8 tf32 mma, fp32 accumulate
__device__ __forceinline__ void mma8(float* c, const uint32_t* a, const uint32_t* b) {
    asm volatile(
        "mma.sync.aligned.m16n8k8.row.col.f32.tf32.tf32.f32 "
        "{%0,%1,%2,%3},{%4,%5,%6,%7},{%8,%9},{%0,%1,%2,%3};\n"
        : "+f"(c[0]), "+f"(c[1]), "+f"(c[2]), "+f"(c[3])
        : "r"(a[0]), "r"(a[1]), "r"(a[2]), "r"(a[3]), "r"(b[0]), "r"(b[1]));
}

// ---------------- LayerNorm: one block per row (D=512, 128 thr x float4) ----------------
__global__ void ln_kernel(const float* __restrict__ x, const float* __restrict__ sc,
                          const float* __restrict__ bi, float* __restrict__ y)
{
    __shared__ float sm[8];
    int row = blockIdx.x;
    int t = threadIdx.x;
    float4 v = reinterpret_cast<const float4*>(x + (size_t)row * DD)[t];
    float s = v.x + v.y + v.z + v.w;
    float q = v.x * v.x + v.y * v.y + v.z * v.z + v.w * v.w;
    s = warp_sum(s); q = warp_sum(q);
    if ((t & 31) == 0) { sm[t >> 5] = s; sm[4 + (t >> 5)] = q; }
    __syncthreads();
    float S = sm[0] + sm[1] + sm[2] + sm[3];
    float Q = sm[4] + sm[5] + sm[6] + sm[7];
    float mean = S * (1.0f / DD);
    float var  = Q * (1.0f / DD) - mean * mean;
    float inv  = rsqrtf(var + 1e-5f);
    float4 scv = reinterpret_cast<const float4*>(sc)[t];
    float4 biv = reinterpret_cast<const float4*>(bi)[t];
    float4 o;
    o.x = (v.x - mean) * inv * scv.x + biv.x;
    o.y = (v.y - mean) * inv * scv.y + biv.y;
    o.z = (v.z - mean) * inv * scv.z + biv.z;
    o.w = (v.w - mean) * inv * scv.w + biv.w;
    reinterpret_cast<float4*>(y + (size_t)row * DD)[t] = o;
}

// ---------------- TF32 tensor-core GEMM: 128x128 block, BK=32, 8 warps (32x64 warp tile) ----------------
// EPI: 0 = +bias, 1 = +bias then gelu, 2 = +bias then +residual
template<int EPI>
__global__ void __launch_bounds__(256)
gemm_tf32(const float* __restrict__ A, const float* __restrict__ B,
          const float* __restrict__ bias, const float* __restrict__ res,
          float* __restrict__ C, int M, int N, int K)
{
    __shared__ float As[128][36];   // [m][k], ld 36 -> frag bank = 4g+tig (conflict-free)
    __shared__ float Bs[32][136];   // [k][n], ld 136 -> frag bank = 8tig+g (conflict-free)
    int tid = threadIdx.x;
    int lane = tid & 31, warp = tid >> 5;
    int g = lane >> 2, tig = lane & 3;
    int wm = (warp >> 1) * 32, wn = (warp & 1) * 64;
    int bm = blockIdx.y * 128, bn = blockIdx.x * 128;

    float c[2][8][4];
#pragma unroll
    for (int i = 0; i < 2; i++)
#pragma unroll
        for (int j = 0; j < 8; j++)
#pragma unroll
            for (int q = 0; q < 4; q++) c[i][j][q] = 0.f;

    float4 ra[4], rb[4];
    // prefetch tile 0
#pragma unroll
    for (int i = 0; i < 4; i++) {
        int idx = tid + i * 256;
        int m = idx >> 3, f = idx & 7;
        ra[i] = *reinterpret_cast<const float4*>(A + (size_t)(bm + m) * K + f * 4);
        int kk = idx >> 5, fb = idx & 31;
        rb[i] = *reinterpret_cast<const float4*>(B + (size_t)kk * N + bn + fb * 4);
    }

    for (int k0 = 0; k0 < K; k0 += 32) {
        __syncthreads();
#pragma unroll
        for (int i = 0; i < 4; i++) {
            int idx = tid + i * 256;
            int m = idx >> 3, f = idx & 7;
            float4 v; v.x = to_tf32(ra[i].x); v.y = to_tf32(ra[i].y);
            v.z = to_tf32(ra[i].z); v.w = to_tf32(ra[i].w);
            *reinterpret_cast<float4*>(&As[m][f * 4]) = v;
            int kk = idx >> 5, fb = idx & 31;
            float4 w; w.x = to_tf32(rb[i].x); w.y = to_tf32(rb[i].y);
            w.z = to_tf32(rb[i].z); w.w = to_tf32(rb[i].w);
            *reinterpret_cast<float4*>(&Bs[kk][fb * 4]) = w;
        }
        __syncthreads();
        if (k0 + 32 < K) {
#pragma unroll
            for (int i = 0; i < 4; i++) {
                int idx = tid + i * 256;
                int m = idx >> 3, f = idx & 7;
                ra[i] = *reinterpret_cast<const float4*>(A + (size_t)(bm + m) * K + k0 + 32 + f * 4);
                int kk = idx >> 5, fb = idx & 31;
                rb[i] = *reinterpret_cast<const float4*>(B + (size_t)(k0 + 32 + kk) * N + bn + fb * 4);
            }
        }
#pragma unroll
        for (int ks = 0; ks < 4; ks++) {
            int k = ks * 8;
            uint32_t af[2][4], bf[8][2];
#pragma unroll
            for (int mt = 0; mt < 2; mt++) {
                int mr = wm + mt * 16 + g;
                af[mt][0] = f2u(As[mr][k + tig]);
                af[mt][1] = f2u(As[mr + 8][k + tig]);
                af[mt][2] = f2u(As[mr][k + tig + 4]);
                af[mt][3] = f2u(As[mr + 8][k + tig + 4]);
            }
#pragma unroll
            for (int nt = 0; nt < 8; nt++) {
                int nc = wn + nt * 8 + g;
                bf[nt][0] = f2u(Bs[k + tig][nc]);
                bf[nt][1] = f2u(Bs[k + tig + 4][nc]);
            }
#pragma unroll
            for (int mt = 0; mt < 2; mt++)
#pragma unroll
                for (int nt = 0; nt < 8; nt++)
                    mma8(c[mt][nt], af[mt], bf[nt]);
        }
    }

#pragma unroll
    for (int mt = 0; mt < 2; mt++) {
        int r0 = bm + wm + mt * 16 + g;
        int r1 = r0 + 8;
#pragma unroll
        for (int nt = 0; nt < 8; nt++) {
            int cc = bn + wn + nt * 8 + tig * 2;
            float b0 = bias[cc], b1 = bias[cc + 1];
            float v00 = c[mt][nt][0] + b0, v01 = c[mt][nt][1] + b1;
            float v10 = c[mt][nt][2] + b0, v11 = c[mt][nt][3] + b1;
            if (EPI == 1) {
                v00 = gelu_tanh(v00); v01 = gelu_tanh(v01);
                v10 = gelu_tanh(v10); v11 = gelu_tanh(v11);
            }
            if (EPI == 2) {
                v00 += res[(size_t)r0 * N + cc]; v01 += res[(size_t)r0 * N + cc + 1];
                v10 += res[(size_t)r1 * N + cc]; v11 += res[(size_t)r1 * N + cc + 1];
            }
            *reinterpret_cast<float2*>(C + (size_t)r0 * N + cc) = make_float2(v00, v01);
            *reinterpret_cast<float2*>(C + (size_t)r1 * N + cc) = make_float2(v10, v11);
        }
    }
}

// ---------------- attention scores (TF32 mma): 64x64 tile, K=dh=64 in one stage ----------------
__global__ void __launch_bounds__(256)
attn_scores_tf32(const float* __restrict__ qkv, float* __restrict__ scores)
{
    __shared__ float Qs[64][68];    // [m][dh]
    __shared__ float Ks[64][72];    // [dh][n] (transposed at staging; ld 72 -> bank 8tig+g)
    int bh = blockIdx.z;
    int b = bh >> 3, h = bh & 7;
    int i0 = blockIdx.y * 64, j0 = blockIdx.x * 64;
    int tid = threadIdx.x;
    int lane = tid & 31, warp = tid >> 5;
    int g = lane >> 2, tig = lane & 3;
    int wm = (warp >> 1) * 16, wn = (warp & 1) * 32;
    const float* qb = qkv + ((size_t)b * LL + i0) * (3 * DD) + h * DH;
    const float* kb = qkv + ((size_t)b * LL + j0) * (3 * DD) + DD + h * DH;

    // stage Q: 64x64 = 1024 float4 (row-major, coalesced)
#pragma unroll
    for (int i = 0; i < 4; i++) {
        int idx = tid + i * 256;
        int m = idx >> 4, f = idx & 15;
        float4 v = *reinterpret_cast<const float4*>(qb + (size_t)m * (3 * DD) + f * 4);
        Qs[m][f * 4 + 0] = to_tf32(v.x); Qs[m][f * 4 + 1] = to_tf32(v.y);
        Qs[m][f * 4 + 2] = to_tf32(v.z); Qs[m][f * 4 + 3] = to_tf32(v.w);
    }
    // stage K transposed: consecutive lanes take consecutive n -> conflict-free STS
#pragma unroll
    for (int i = 0; i < 4; i++) {
        int idx = tid + i * 256;
        int n = idx & 63, f = idx >> 6;
        float4 v = *reinterpret_cast<const float4*>(kb + (size_t)n * (3 * DD) + f * 4);
        Ks[f * 4 + 0][n] = to_tf32(v.x); Ks[f * 4 + 1][n] = to_tf32(v.y);
        Ks[f * 4 + 2][n] = to_tf32(v.z); Ks[f * 4 + 3][n] = to_tf32(v.w);
    }
    __syncthreads();

    float c[4][4];
#pragma unroll
    for (int j = 0; j < 4; j++)
#pragma unroll
        for (int q = 0; q < 4; q++) c[j][q] = 0.f;

#pragma unroll
    for (int ks = 0; ks < 8; ks++) {
        int k = ks * 8;
        uint32_t af[4], bf[4][2];
        int mr = wm + g;
        af[0] = f2u(Qs[mr][k + tig]);
        af[1] = f2u(Qs[mr + 8][k + tig]);
        af[2] = f2u(Qs[mr][k + tig + 4]);
        af[3] = f2u(Qs[mr + 8][k + tig + 4]);
#pragma unroll
        for (int nt = 0; nt < 4; nt++) {
            int nc = wn + nt * 8 + g;
            bf[nt][0] = f2u(Ks[k + tig][nc]);
            bf[nt][1] = f2u(Ks[k + tig + 4][nc]);
        }
#pragma unroll
        for (int nt = 0; nt < 4; nt++) mma8(c[nt], af, bf[nt]);
    }

    float* out = scores + ((size_t)bh * LL + i0) * LL + j0;
    int r0 = wm + g, r1 = r0 + 8;
#pragma unroll
    for (int nt = 0; nt < 4; nt++) {
        int cc = wn + nt * 8 + tig * 2;
        *reinterpret_cast<float2*>(out + (size_t)r0 * LL + cc) =
            make_float2(c[nt][0] * 0.125f, c[nt][1] * 0.125f);
        *reinterpret_cast<float2*>(out + (size_t)r1 * LL + cc) =
            make_float2(c[nt][2] * 0.125f, c[nt][3] * 0.125f);
    }
}

// ---------------- row softmax over 512 ----------------
__global__ void softmax_kernel(float* __restrict__ scores)
{
    __shared__ float sm[8];
    size_t row = blockIdx.x;
    int t = threadIdx.x;  // 128
    float4* p = reinterpret_cast<float4*>(scores + row * (size_t)LL);
    float4 v = p[t];
    float m = fmaxf(fmaxf(v.x, v.y), fmaxf(v.z, v.w));
    m = warp_max(m);
    if ((t & 31) == 0) sm[t >> 5] = m;
    __syncthreads();
    m = fmaxf(fmaxf(sm[0], sm[1]), fmaxf(sm[2], sm[3]));
    v.x = __expf(v.x - m); v.y = __expf(v.y - m);
    v.z = __expf(v.z - m); v.w = __expf(v.w - m);
    float s = v.x + v.y + v.z + v.w;
    s = warp_sum(s);
    if ((t & 31) == 0) sm[4 + (t >> 5)] = s;
    __syncthreads();
    s = sm[4] + sm[5] + sm[6] + sm[7];
    float inv = __frcp_rn(s);
    v.x *= inv; v.y *= inv; v.z *= inv; v.w *= inv;
    p[t] = v;
}

// ---------------- attn @ V (TF32 mma): 128-row tile x dh=64, K=512 ----------------
__global__ void __launch_bounds__(256)
attn_av_tf32(const float* __restrict__ scores, const float* __restrict__ qkv,
             float* __restrict__ o)
{
    __shared__ float Ss[128][36];   // [m][k]
    __shared__ float Vs[32][72];    // [k][n], natural layout of V, ld 72 conflict-free
    int bh = blockIdx.y;
    int b = bh >> 3, h = bh & 7;
    int i0 = blockIdx.x * 128;
    int tid = threadIdx.x;
    int lane = tid & 31, warp = tid >> 5;
    int g = lane >> 2, tig = lane & 3;
    int wm = (warp >> 1) * 32, wn = (warp & 1) * 32;
    const float* sb = scores + ((size_t)bh * LL + i0) * LL;
    const float* vb = qkv + (size_t)b * LL * (3 * DD) + 2 * DD + h * DH;

    float c[2][4][4];
#pragma unroll
    for (int i = 0; i < 2; i++)
#pragma unroll
        for (int j = 0; j < 4; j++)
#pragma unroll
            for (int q = 0; q < 4; q++) c[i][j][q] = 0.f;

    float4 ra[4], rb[2];
#pragma unroll
    for (int i = 0; i < 4; i++) {
        int idx = tid + i * 256;
        int m = idx >> 3, f = idx & 7;
        ra[i] = *reinterpret_cast<const float4*>(sb + (size_t)m * LL + f * 4);
    }
#pragma unroll
    for (int i = 0; i < 2; i++) {
        int idx = tid + i * 256;
        int k = idx >> 4, f = idx & 15;
        rb[i] = *reinterpret_cast<const float4*>(vb + (size_t)k * (3 * DD) + f * 4);
    }

    for (int k0 = 0; k0 < LL; k0 += 32) {
        __syncthreads();
#pragma unroll
        for (int i = 0; i < 4; i++) {
            int idx = tid + i * 256;
            int m = idx >> 3, f = idx & 7;
            float4 v; v.x = to_tf32(ra[i].x); v.y = to_tf32(ra[i].y);
            v.z = to_tf32(ra[i].z); v.w = to_tf32(ra[i].w);
            *reinterpret_cast<float4*>(&Ss[m][f * 4]) = v;
        }
#pragma unroll
        for (int i = 0; i < 2; i++) {
            int idx = tid + i * 256;
            int k = idx >> 4, f = idx & 15;
            float4 v; v.x = to_tf32(rb[i].x); v.y = to_tf32(rb[i].y);
            v.z = to_tf32(rb[i].z); v.w = to_tf32(rb[i].w);
            *reinterpret_cast<float4*>(&Vs[k][f * 4]) = v;
        }
        __syncthreads();
        if (k0 + 32 < LL) {
#pragma unroll
            for (int i = 0; i < 4; i++) {
                int idx = tid + i * 256;
                int m = idx >> 3, f = idx & 7;
                ra[i] = *reinterpret_cast<const float4*>(sb + (size_t)m * LL + k0 + 32 + f * 4);
            }
#pragma unroll
            for (int i = 0; i < 2; i++) {
                int idx = tid + i * 256;
                int k = idx >> 4, f = idx & 15;
                rb[i] = *reinterpret_cast<const float4*>(vb + (size_t)(k0 + 32 + k) * (3 * DD) + f * 4);
            }
        }
#pragma unroll
        for (int ks = 0; ks < 4; ks++) {
            int k = ks * 8;
            uint32_t af[2][4], bf[4][2];
#pragma unroll
            for (int mt = 0; mt < 2; mt++) {
                int mr = wm + mt * 16 + g;
                af[mt][0] = f2u(Ss[mr][k + tig]);
                af[mt][1] = f2u(Ss[mr + 8][k + tig]);
                af[mt][2] = f2u(Ss[mr][k + tig + 4]);
                af[mt][3] = f2u(Ss[mr + 8][k + tig + 4]);
            }
#pragma unroll
            for (int nt = 0; nt < 4; nt++) {
                int nc = wn + nt * 8 + g;
                bf[nt][0] = f2u(Vs[k + tig][nc]);
                bf[nt][1] = f2u(Vs[k + tig + 4][nc]);
            }
#pragma unroll
            for (int mt = 0; mt < 2; mt++)
#pragma unroll
                for (int nt = 0; nt < 4; nt++)
                    mma8(c[mt][nt], af[mt], bf[nt]);
        }
    }

#pragma unroll
    for (int mt = 0; mt < 2; mt++) {
        int r0 = i0 + wm + mt * 16 + g;
        int r1 = r0 + 8;
#pragma unroll
        for (int nt = 0; nt < 4; nt++) {
            int cc = h * DH + wn + nt * 8 + tig * 2;
            *reinterpret_cast<float2*>(o + ((size_t)b * LL + r0) * DD + cc) =
                make_float2(c[mt][nt][0], c[mt][nt][1]);
            *reinterpret_cast<float2*>(o + ((size_t)b * LL + r1) * DD + cc) =
                make_float2(c[mt][nt][2], c[mt][nt][3]);
        }
    }
}

// ---------------- accumulate expert output into sum; column sums into meaneo ----------------
__global__ void accum_colmean_kernel(const float* __restrict__ xout, float* __restrict__ sum,
                                     float* __restrict__ meaneo, int first)
{
    int t = threadIdx.x;
    int r0 = blockIdx.x * 128;
    float local = 0.f;
    for (int r = r0; r < r0 + 128; r++) {
        size_t idx = (size_t)r * DD + t;
        float v = xout[idx];
        local += v;
        if (first) sum[idx] = v; else sum[idx] += v;
    }
    atomicAdd(&meaneo[t], local);
}

// ---------------- sum / sum^2 of (x - recon) ----------------
__global__ void uvar_kernel(const float* __restrict__ x, const float* __restrict__ sum,
                            float* __restrict__ stats)
{
    __shared__ float sm[16];
    float s1 = 0.f, s2 = 0.f;
    for (size_t i = (size_t)blockIdx.x * blockDim.x + threadIdx.x; i < NELEM;
         i += (size_t)gridDim.x * blockDim.x) {
        float d = x[i] - 0.25f * sum[i];
        s1 += d; s2 += d * d;
    }
    s1 = warp_sum(s1); s2 = warp_sum(s2);
    int w = threadIdx.x >> 5;
    if ((threadIdx.x & 31) == 0) { sm[w] = s1; sm[8 + w] = s2; }
    __syncthreads();
    if (threadIdx.x == 0) {
        float a = 0.f, b = 0.f;
        for (int i = 0; i < 8; i++) { a += sm[i]; b += sm[8 + i]; }
        atomicAdd(&stats[0], a);
        atomicAdd(&stats[1], b);
    }
}

// ---------------- gram / ortho / uvar / rate ----------------
__global__ void finalize_kernel(const float* __restrict__ meaneo, float* __restrict__ stats)
{
    __shared__ float sd[16];
    int t = threadIdx.x;  // 256
    if (t < 16) sd[t] = 0.f;
    __syncthreads();
    float l[4][4] = {};
    for (int c = t; c < DD; c += 256) {
        float v[4];
#pragma unroll
        for (int i = 0; i < 4; i++) v[i] = meaneo[i * DD + c];
#pragma unroll
        for (int i = 0; i < 4; i++)
#pragma unroll
            for (int j = i; j < 4; j++) l[i][j] += v[i] * v[j];
    }
#pragma unroll
    for (int i = 0; i < 4; i++)
#pragma unroll
        for (int j = i; j < 4; j++) atomicAdd(&sd[i * 4 + j], l[i][j]);
    __syncthreads();
    if (t == 0) {
        float nrm[4];
        for (int i = 0; i < 4; i++) nrm[i] = sqrtf(sd[i * 4 + i]);
        float off = 0.f;
        for (int i = 0; i < 4; i++)
            for (int j = 0; j < 4; j++) {
                float dot = (i <= j) ? sd[i * 4 + j] : sd[j * 4 + i];
                float g = dot / (nrm[i] * nrm[j]);
                float dlt = g - (i == j ? 1.0f : 0.0f);
                off += dlt * dlt;
            }
        float ortho = 1.0f - off / 16.0f;
        float S1 = stats[0], S2 = stats[1];
        const float N = (float)NELEM;
        float uvar = (S2 - S1 * S1 / N) / (N - 1.0f);
        float sat = ortho * uvar;
        stats[2] = (sat > 0.01f) ? 0.01f : 0.0f;
    }
}

// ---------------- final combine: (sum_prim + rate * ghost0) / 6 ----------------
__global__ void combine_kernel(const float* __restrict__ sum, const float* __restrict__ ghost,
                               const float* __restrict__ stats, float* __restrict__ out)
{
    float rate = stats[2];
    const float inv6 = 1.0f / 6.0f;
    size_t stride = (size_t)gridDim.x * blockDim.x;
    for (size_t i = (size_t)blockIdx.x * blockDim.x + threadIdx.x; i < NELEM / 4; i += stride) {
        float4 s = reinterpret_cast<const float4*>(sum)[i];
        float4 g = reinterpret_cast<const float4*>(ghost)[i];
        float4 o;
        o.x = (s.x + rate * g.x) * inv6;
        o.y = (s.y + rate * g.y) * inv6;
        o.z = (s.z + rate * g.z) * inv6;
        o.w = (s.w + rate * g.w) * inv6;
        reinterpret_cast<float4*>(out)[i] = o;
    }
}

// ---------------- orchestration ----------------
struct ExpertW {
    const float *ln1_s, *ln1_b, *wqkv, *bqkv, *wo, *bo, *ln2_s, *ln2_b, *w1, *b1, *w2, *b2;
};

static void run_expert(const float* x, const ExpertW& w,
                       float* xn, float* qkv, float* scores, float* attno,
                       float* x2, float* ffh, float* xout)
{
    ln_kernel<<<BL, 128>>>(x, w.ln1_s, w.ln1_b, xn);
    gemm_tf32<0><<<dim3(3 * DD / 128, BL / 128), 256>>>(xn, w.wqkv, w.bqkv, nullptr, qkv, BL, 3 * DD, DD);
    attn_scores_tf32<<<dim3(LL / 64, LL / 64, BB * HH), 256>>>(qkv, scores);
    softmax_kernel<<<BB * HH * LL, 128>>>(scores);
    attn_av_tf32<<<dim3(LL / 128, BB * HH), 256>>>(scores, qkv, attno);
    gemm_tf32<2><<<dim3(DD / 128, BL / 128), 256>>>(attno, w.wo, w.bo, x, x2, BL, DD, DD);
    ln_kernel<<<BL, 128>>>(x2, w.ln2_s, w.ln2_b, xn);
    gemm_tf32<1><<<dim3(4 * DD / 128, BL / 128), 256>>>(xn, w.w1, w.b1, nullptr, ffh, BL, 4 * DD, DD);
    gemm_tf32<2><<<dim3(DD / 128, BL / 128), 256>>>(ffh, w.w2, w.b2, x2, xout, BL, DD, 4 * DD);
}

extern "C" void kernel_launch(void* const* d_in, const int* in_sizes, int n_in,
                              void* d_out, int out_size)
{
    const float* x = (const float*)d_in[0];
    const float* p[12];
    const float* g[12];
    for (int i = 0; i < 12; i++) p[i] = (const float*)d_in[2 + i];
    for (int i = 0; i < 12; i++) g[i] = (const float*)d_in[14 + i];

    float *xn, *qkv, *scores, *attno, *x2, *ffh, *xout, *sum, *meaneo, *stats;
    cudaGetSymbolAddress((void**)&xn, d_xn);
    cudaGetSymbolAddress((void**)&qkv, d_qkv);
    cudaGetSymbolAddress((void**)&scores, d_scores);
    cudaGetSymbolAddress((void**)&attno, d_attno);
    cudaGetSymbolAddress((void**)&x2, d_x2);
    cudaGetSymbolAddress((void**)&ffh, d_ffh);
    cudaGetSymbolAddress((void**)&xout, d_xout);
    cudaGetSymbolAddress((void**)&sum, d_sum);
    cudaGetSymbolAddress((void**)&meaneo, d_meaneo);
    cudaGetSymbolAddress((void**)&stats, d_stats);

    cudaMemsetAsync(meaneo, 0, 4 * DD * sizeof(float));
    cudaMemsetAsync(stats, 0, 4 * sizeof(float));

    const size_t str[12] = { DD, DD, (size_t)DD * 3 * DD, 3 * DD, (size_t)DD * DD, DD,
                             DD, DD, (size_t)DD * 4 * DD, 4 * DD, (size_t)4 * DD * DD, DD };

    for (int e = 0; e < 4; e++) {
        ExpertW w;
        const float** f = (const float**)&w;
        for (int i = 0; i < 12; i++) f[i] = p[i] + (size_t)e * str[i];
        run_expert(x, w, xn, qkv, scores, attno, x2, ffh, xout);
        accum_colmean_kernel<<<32, 512>>>(xout, sum, meaneo + e * DD, e == 0);
    }

    uvar_kernel<<<512, 256>>>(x, sum, stats);
    finalize_kernel<<<1, 256>>>(meaneo, stats);

    // ghost expert 0 (ghost 1 has rate 0 always -> skipped)
    {
        ExpertW w;
        const float** f = (const float**)&w;
        for (int i = 0; i < 12; i++) f[i] = g[i];
        run_expert(x, w, xn, qkv, scores, attno, x2, ffh, xout);
    }

    combine_kernel<<<1024, 256>>>(sum, xout, stats, (float*)d_out);
}

// round 4
// speedup vs baseline: 4.5706x; 1.8531x over previous
#include <cuda_runtime.h>
#include <math.h>
#include <stdint.h>

#define BB 8
#define LL 512
#define DD 512
#define HH 8
#define DH 64
#define BL 4096                 // B*L rows
#define NELEM 2097152           // B*L*D
#define NE 5                    // 4 primary + ghost0

// ---------------- scratch (static device globals; no allocation) ----------------
__device__ float d_xn[NE * BL * DD];            // LN output (tf32-rounded)
__device__ float d_qkv[(size_t)NE * BL * 3 * DD]; // QKV (tf32-rounded)
__device__ float d_attno[NE * BL * DD];         // attention out (tf32-rounded)
__device__ float d_x2[NE * BL * DD];            // after attn residual (fp32)
__device__ float d_ffh[(size_t)NE * BL * 4 * DD]; // FFN hidden (tf32-rounded)
__device__ float d_xout[NE * BL * DD];          // expert outputs (fp32)
__device__ float d_wqkvt[(size_t)NE * DD * 3 * DD];
__device__ float d_wot[(size_t)NE * DD * DD];
__device__ float d_w1t[(size_t)NE * DD * 4 * DD];
__device__ float d_w2t[(size_t)NE * 4 * DD * DD];
__device__ float d_meaneo[4 * DD];
__device__ float d_stats[4];

// ---------------- helpers ----------------
__device__ __forceinline__ float warp_sum(float v) {
#pragma unroll
    for (int o = 16; o > 0; o >>= 1) v += __shfl_xor_sync(0xffffffffu, v, o);
    return v;
}
__device__ __forceinline__ float gelu_tanh(float v) {
    float c = 0.7978845608028654f * (v + 0.044715f * v * v * v);
    return 0.5f * v * (1.0f + tanhf(c));
}
__device__ __forceinline__ float to_tf32(float x) {
    float r;
    asm("cvt.rna.tf32.f32 %0, %1;" : "=f"(r) : "f"(x));
    return r;
}
__device__ __forceinline__ uint32_t f2u(float x) { return __float_as_uint(x); }

__device__ __forceinline__ void mma8(float* c, const uint32_t* a, const uint32_t* b) {
    asm volatile(
        "mma.sync.aligned.m16n8k8.row.col.f32.tf32.tf32.f32 "
        "{%0,%1,%2,%3},{%4,%5,%6,%7},{%8,%9},{%0,%1,%2,%3};\n"
        : "+f"(c[0]), "+f"(c[1]), "+f"(c[2]), "+f"(c[3])
        : "r"(a[0]), "r"(a[1]), "r"(a[2]), "r"(a[3]), "r"(b[0]), "r"(b[1]));
}

__device__ __forceinline__ void cpa16(void* dst, const void* src) {
    uint32_t d = (uint32_t)__cvta_generic_to_shared(dst);
    asm volatile("cp.async.cg.shared.global [%0], [%1], 16;\n" :: "r"(d), "l"(src));
}
#define CP_COMMIT() asm volatile("cp.async.commit_group;\n" ::: "memory")
#define CP_WAIT1()  asm volatile("cp.async.wait_group 1;\n" ::: "memory")

// ---------------- weight pre-rounding: [4n primary | n ghost0] -> [5][n] tf32 ----------------
__global__ void roundw_kernel(const float* __restrict__ p, const float* __restrict__ g,
                              float* __restrict__ o, size_t n)
{
    size_t n4 = n >> 2;           // float4 count per expert
    size_t tot = 5 * n4;
    size_t stride = (size_t)gridDim.x * blockDim.x;
    for (size_t i = (size_t)blockIdx.x * blockDim.x + threadIdx.x; i < tot; i += stride) {
        float4 v = (i < 4 * n4) ? reinterpret_cast<const float4*>(p)[i]
                                : reinterpret_cast<const float4*>(g)[i - 4 * n4];
        v.x = to_tf32(v.x); v.y = to_tf32(v.y); v.z = to_tf32(v.z); v.w = to_tf32(v.w);
        reinterpret_cast<float4*>(o)[i] = v;
    }
}

// ---------------- LayerNorm over 5 experts; output rounded to tf32 ----------------
__global__ void ln5_kernel(const float* __restrict__ X, size_t sX, int xShared,
                           const float* __restrict__ sP, const float* __restrict__ sG,
                           const float* __restrict__ bP, const float* __restrict__ bG,
                           float* __restrict__ Y)
{
    __shared__ float sm[8];
    int e = blockIdx.y;
    const float* x = (xShared ? X : X + (size_t)e * sX) + (size_t)blockIdx.x * DD;
    const float* sc = (e < 4 ? sP + (size_t)e * DD : sG);
    const float* bi = (e < 4 ? bP + (size_t)e * DD : bG);
    float* y = Y + (size_t)e * NELEM + (size_t)blockIdx.x * DD;
    int t = threadIdx.x;
    float4 v = reinterpret_cast<const float4*>(x)[t];
    float s = v.x + v.y + v.z + v.w;
    float q = v.x * v.x + v.y * v.y + v.z * v.z + v.w * v.w;
    s = warp_sum(s); q = warp_sum(q);
    if ((t & 31) == 0) { sm[t >> 5] = s; sm[4 + (t >> 5)] = q; }
    __syncthreads();
    float S = sm[0] + sm[1] + sm[2] + sm[3];
    float Q = sm[4] + sm[5] + sm[6] + sm[7];
    float mean = S * (1.0f / DD);
    float var  = Q * (1.0f / DD) - mean * mean;
    float inv  = rsqrtf(var + 1e-5f);
    float4 scv = reinterpret_cast<const float4*>(sc)[t];
    float4 biv = reinterpret_cast<const float4*>(bi)[t];
    float4 o;
    o.x = to_tf32((v.x - mean) * inv * scv.x + biv.x);
    o.y = to_tf32((v.y - mean) * inv * scv.y + biv.y);
    o.z = to_tf32((v.z - mean) * inv * scv.z + biv.z);
    o.w = to_tf32((v.w - mean) * inv * scv.w + biv.w);
    reinterpret_cast<float4*>(y)[t] = o;
}

// ---------------- GEMM v2: 128x128 tiles, BK=32, cp.async 3-stage, 5-expert z ----------------
// inputs pre-rounded to tf32. EPI: 0=+bias(+rnd), 1=+bias,gelu(+rnd), 2=+bias,+residual
#define ASW (128 * 36)
#define BSW (32 * 136)
#define STGW (ASW + BSW)

template<int EPI, bool RND>
__global__ void __launch_bounds__(256)
gemm5(const float* __restrict__ Ab, size_t sA,
      const float* __restrict__ Wb, size_t sW,
      const float* __restrict__ bP, const float* __restrict__ bG, int sB,
      const float* __restrict__ Rb, size_t sR, int rShared,
      float* __restrict__ Cb, size_t sC, int N, int K)
{
    extern __shared__ float smemf[];
    int e = blockIdx.z;
    const float* A = Ab + (size_t)e * sA;
    const float* W = Wb + (size_t)e * sW;
    const float* bias = (e < 4 ? bP + (size_t)e * sB : bG);
    const float* R = Rb ? (rShared ? Rb : Rb + (size_t)e * sR) : nullptr;
    float* C = Cb + (size_t)e * sC;

    int tid = threadIdx.x;
    int lane = tid & 31, warp = tid >> 5;
    int g = lane >> 2, tig = lane & 3;
    int wm = (warp >> 1) * 32, wn = (warp & 1) * 64;
    int bm = blockIdx.y * 128, bn = blockIdx.x * 128;

    float c[2][8][4];
#pragma unroll
    for (int i = 0; i < 2; i++)
#pragma unroll
        for (int j = 0; j < 8; j++)
#pragma unroll
            for (int q = 0; q < 4; q++) c[i][j][q] = 0.f;

    int KT = K >> 5;

    // prologue: stage 0, 1
#pragma unroll
    for (int s = 0; s < 2; s++) {
        float* As = smemf + s * STGW;
        float* Bs = As + ASW;
        int k0 = s * 32;
#pragma unroll
        for (int i = 0; i < 4; i++) {
            int idx = tid + i * 256;
            int row = idx >> 3, c4 = idx & 7;
            cpa16(As + row * 36 + c4 * 4, A + (size_t)(bm + row) * K + k0 + c4 * 4);
        }
#pragma unroll
        for (int i = 0; i < 4; i++) {
            int idx = tid + i * 256;
            int row = idx >> 5, c4 = idx & 31;
            cpa16(Bs + row * 136 + c4 * 4, W + (size_t)(k0 + row) * N + bn + c4 * 4);
        }
        CP_COMMIT();
    }

    for (int it = 0; it < KT; it++) {
        CP_WAIT1();
        __syncthreads();
        const float* As = smemf + (it % 3) * STGW;
        const float* Bs = As + ASW;
#pragma unroll
        for (int ks = 0; ks < 4; ks++) {
            int k = ks * 8;
            uint32_t af[2][4], bf[8][2];
#pragma unroll
            for (int mt = 0; mt < 2; mt++) {
                int mr = wm + mt * 16 + g;
                af[mt][0] = f2u(As[mr * 36 + k + tig]);
                af[mt][1] = f2u(As[(mr + 8) * 36 + k + tig]);
                af[mt][2] = f2u(As[mr * 36 + k + tig + 4]);
                af[mt][3] = f2u(As[(mr + 8) * 36 + k + tig + 4]);
            }
#pragma unroll
            for (int nt = 0; nt < 8; nt++) {
                int nc = wn + nt * 8 + g;
                bf[nt][0] = f2u(Bs[(k + tig) * 136 + nc]);
                bf[nt][1] = f2u(Bs[(k + tig + 4) * 136 + nc]);
            }
#pragma unroll
            for (int mt = 0; mt < 2; mt++)
#pragma unroll
                for (int nt = 0; nt < 8; nt++)
                    mma8(c[mt][nt], af[mt], bf[nt]);
        }
        int nx = it + 2;
        if (nx < KT) {
            float* Asw = smemf + (nx % 3) * STGW;
            float* Bsw = Asw + ASW;
            int k0 = nx * 32;
#pragma unroll
            for (int i = 0; i < 4; i++) {
                int idx = tid + i * 256;
                int row = idx >> 3, c4 = idx & 7;
                cpa16(Asw + row * 36 + c4 * 4, A + (size_t)(bm + row) * K + k0 + c4 * 4);
            }
#pragma unroll
            for (int i = 0; i < 4; i++) {
                int idx = tid + i * 256;
                int row = idx >> 5, c4 = idx & 31;
                cpa16(Bsw + row * 136 + c4 * 4, W + (size_t)(k0 + row) * N + bn + c4 * 4);
            }
        }
        CP_COMMIT();
    }

#pragma unroll
    for (int mt = 0; mt < 2; mt++) {
        int r0 = bm + wm + mt * 16 + g;
        int r1 = r0 + 8;
#pragma unroll
        for (int nt = 0; nt < 8; nt++) {
            int cc = bn + wn + nt * 8 + tig * 2;
            float b0 = bias[cc], b1 = bias[cc + 1];
            float v00 = c[mt][nt][0] + b0, v01 = c[mt][nt][1] + b1;
            float v10 = c[mt][nt][2] + b0, v11 = c[mt][nt][3] + b1;
            if (EPI == 1) {
                v00 = gelu_tanh(v00); v01 = gelu_tanh(v01);
                v10 = gelu_tanh(v10); v11 = gelu_tanh(v11);
            }
            if (EPI == 2) {
                v00 += R[(size_t)r0 * N + cc]; v01 += R[(size_t)r0 * N + cc + 1];
                v10 += R[(size_t)r1 * N + cc]; v11 += R[(size_t)r1 * N + cc + 1];
            }
            if (RND) {
                v00 = to_tf32(v00); v01 = to_tf32(v01);
                v10 = to_tf32(v10); v11 = to_tf32(v11);
            }
            *reinterpret_cast<float2*>(C + (size_t)r0 * N + cc) = make_float2(v00, v01);
            *reinterpret_cast<float2*>(C + (size_t)r1 * N + cc) = make_float2(v10, v11);
        }
    }
}

// ---------------- flash attention: Q-tile 128 x dh 64, j-tiles of 64, online softmax ----------------
// smem: Qs[128][68], Pq[128][68], Ks[64][72] (transposed), Vs[64][72]
#define FQ_OFF 0
#define FP_OFF (128 * 68)
#define FK_OFF (FP_OFF + 128 * 68)
#define FV_OFF (FK_OFF + 64 * 72)
#define FLASH_SMEM ((FV_OFF + 64 * 72) * 4)

__global__ void __launch_bounds__(256)
flash_kernel(const float* __restrict__ qkv5, float* __restrict__ attno5)
{
    extern __shared__ float smemf[];
    float* Qs = smemf + FQ_OFF;
    float* Pq = smemf + FP_OFF;
    float* Ks = smemf + FK_OFF;
    float* Vs = smemf + FV_OFF;

    int e = blockIdx.z;
    const float* qkv = qkv5 + (size_t)e * BL * 3 * DD;
    float* attno = attno5 + (size_t)e * NELEM;
    int bh = blockIdx.y;
    int b = bh >> 3, h = bh & 7;
    int i0 = blockIdx.x * 128;
    int tid = threadIdx.x;
    int lane = tid & 31, warp = tid >> 5;
    int g = lane >> 2, tig = lane & 3;
    int wm = warp * 16;

    // stage Q (scaled by 1/sqrt(dh)=0.125; exact power of 2 keeps tf32)
#pragma unroll
    for (int i = 0; i < 8; i++) {
        int idx = tid + i * 256;
        int m = idx >> 4, f = idx & 15;
        float4 v = *reinterpret_cast<const float4*>(
            qkv + ((size_t)(b * LL + i0 + m)) * (3 * DD) + h * DH + f * 4);
        float4 o; o.x = v.x * 0.125f; o.y = v.y * 0.125f; o.z = v.z * 0.125f; o.w = v.w * 0.125f;
        *reinterpret_cast<float4*>(&Qs[m * 68 + f * 4]) = o;
    }

    float o[8][4];
#pragma unroll
    for (int j = 0; j < 8; j++)
#pragma unroll
        for (int q = 0; q < 4; q++) o[j][q] = 0.f;
    float mrow[2] = { -1e30f, -1e30f };
    float lrow[2] = { 0.f, 0.f };

    for (int jt = 0; jt < 8; jt++) {
        int j0 = jt * 64;
        __syncthreads();          // protects Ks/Vs (and first iter: Qs staging)
        // stage K transposed: Ks[dh][n]
#pragma unroll
        for (int i = 0; i < 4; i++) {
            int idx = tid + i * 256;
            int n = idx & 63, f = idx >> 6;
            float4 v = *reinterpret_cast<const float4*>(
                qkv + ((size_t)(b * LL + j0 + n)) * (3 * DD) + DD + h * DH + f * 4);
            Ks[(f * 4 + 0) * 72 + n] = v.x; Ks[(f * 4 + 1) * 72 + n] = v.y;
            Ks[(f * 4 + 2) * 72 + n] = v.z; Ks[(f * 4 + 3) * 72 + n] = v.w;
        }
        // stage V natural: Vs[j][dh]
#pragma unroll
        for (int i = 0; i < 4; i++) {
            int idx = tid + i * 256;
            int kr = idx >> 4, f = idx & 15;
            float4 v = *reinterpret_cast<const float4*>(
                qkv + ((size_t)(b * LL + j0 + kr)) * (3 * DD) + 2 * DD + h * DH + f * 4);
            *reinterpret_cast<float4*>(&Vs[kr * 72 + f * 4]) = v;
        }
        __syncthreads();

        // S = Q @ K^T  (16x64 per warp)
        float c[8][4];
#pragma unroll
        for (int j = 0; j < 8; j++)
#pragma unroll
            for (int q = 0; q < 4; q++) c[j][q] = 0.f;
#pragma unroll
        for (int ks = 0; ks < 8; ks++) {
            int k = ks * 8;
            uint32_t af[4], bf[8][2];
            int mr = wm + g;
            af[0] = f2u(Qs[mr * 68 + k + tig]);
            af[1] = f2u(Qs[(mr + 8) * 68 + k + tig]);
            af[2] = f2u(Qs[mr * 68 + k + tig + 4]);
            af[3] = f2u(Qs[(mr + 8) * 68 + k + tig + 4]);
#pragma unroll
            for (int nt = 0; nt < 8; nt++) {
                int nc = nt * 8 + g;
                bf[nt][0] = f2u(Ks[(k + tig) * 72 + nc]);
                bf[nt][1] = f2u(Ks[(k + tig + 4) * 72 + nc]);
            }
#pragma unroll
            for (int nt = 0; nt < 8; nt++) mma8(c[nt], af, bf[nt]);
        }

        // online softmax update (rows g, g+8 per thread; stats shared across quad)
        float mx0 = -1e30f, mx1 = -1e30f;
#pragma unroll
        for (int nt = 0; nt < 8; nt++) {
            mx0 = fmaxf(mx0, fmaxf(c[nt][0], c[nt][1]));
            mx1 = fmaxf(mx1, fmaxf(c[nt][2], c[nt][3]));
        }
        mx0 = fmaxf(mx0, __shfl_xor_sync(0xffffffffu, mx0, 1));
        mx0 = fmaxf(mx0, __shfl_xor_sync(0xffffffffu, mx0, 2));
        mx1 = fmaxf(mx1, __shfl_xor_sync(0xffffffffu, mx1, 1));
        mx1 = fmaxf(mx1, __shfl_xor_sync(0xffffffffu, mx1, 2));
        float mn0 = fmaxf(mrow[0], mx0), mn1 = fmaxf(mrow[1], mx1);
        float sc0 = __expf(mrow[0] - mn0), sc1 = __expf(mrow[1] - mn1);
        mrow[0] = mn0; mrow[1] = mn1;
        float rs0 = 0.f, rs1 = 0.f;
#pragma unroll
        for (int nt = 0; nt < 8; nt++) {
            c[nt][0] = __expf(c[nt][0] - mn0); c[nt][1] = __expf(c[nt][1] - mn0);
            c[nt][2] = __expf(c[nt][2] - mn1); c[nt][3] = __expf(c[nt][3] - mn1);
            rs0 += c[nt][0] + c[nt][1];
            rs1 += c[nt][2] + c[nt][3];
            o[nt][0] *= sc0; o[nt][1] *= sc0; o[nt][2] *= sc1; o[nt][3] *= sc1;
        }
        rs0 += __shfl_xor_sync(0xffffffffu, rs0, 1);
        rs0 += __shfl_xor_sync(0xffffffffu, rs0, 2);
        rs1 += __shfl_xor_sync(0xffffffffu, rs1, 1);
        rs1 += __shfl_xor_sync(0xffffffffu, rs1, 2);
        lrow[0] = lrow[0] * sc0 + rs0;
        lrow[1] = lrow[1] * sc1 + rs1;

        // write P (tf32) to this warp's private rows of Pq
#pragma unroll
        for (int nt = 0; nt < 8; nt++) {
            int cc = nt * 8 + tig * 2;
            Pq[(wm + g) * 68 + cc]     = to_tf32(c[nt][0]);
            Pq[(wm + g) * 68 + cc + 1] = to_tf32(c[nt][1]);
            Pq[(wm + g + 8) * 68 + cc]     = to_tf32(c[nt][2]);
            Pq[(wm + g + 8) * 68 + cc + 1] = to_tf32(c[nt][3]);
        }
        __syncwarp();

        // O += P @ V
#pragma unroll
        for (int ks = 0; ks < 8; ks++) {
            int k = ks * 8;
            uint32_t af[4], bf[8][2];
            int mr = wm + g;
            af[0] = f2u(Pq[mr * 68 + k + tig]);
            af[1] = f2u(Pq[(mr + 8) * 68 + k + tig]);
            af[2] = f2u(Pq[mr * 68 + k + tig + 4]);
            af[3] = f2u(Pq[(mr + 8) * 68 + k + tig + 4]);
#pragma unroll
            for (int nt = 0; nt < 8; nt++) {
                int nc = nt * 8 + g;
                bf[nt][0] = f2u(Vs[(k + tig) * 72 + nc]);
                bf[nt][1] = f2u(Vs[(k + tig + 4) * 72 + nc]);
            }
#pragma unroll
            for (int nt = 0; nt < 8; nt++) mma8(o[nt], af, bf[nt]);
        }
        __syncwarp();
    }

    float inv0 = __frcp_rn(lrow[0]), inv1 = __frcp_rn(lrow[1]);
    int r0 = i0 + wm + g, r1 = r0 + 8;
#pragma unroll
    for (int nt = 0; nt < 8; nt++) {
        int cc = h * DH + nt * 8 + tig * 2;
        *reinterpret_cast<float2*>(attno + ((size_t)(b * LL + r0)) * DD + cc) =
            make_float2(to_tf32(o[nt][0] * inv0), to_tf32(o[nt][1] * inv0));
        *reinterpret_cast<float2*>(attno + ((size_t)(b * LL + r1)) * DD + cc) =
            make_float2(to_tf32(o[nt][2] * inv1), to_tf32(o[nt][3] * inv1));
    }
}

// ---------------- per-primary-expert column sums ----------------
__global__ void meaneo_kernel(const float* __restrict__ xout5, float* __restrict__ meaneo)
{
    int e = blockIdx.y;
    const float* xo = xout5 + (size_t)e * NELEM;
    int t = threadIdx.x;
    int r0 = blockIdx.x * 128;
    float local = 0.f;
    for (int r = r0; r < r0 + 128; r++) local += xo[(size_t)r * DD + t];
    atomicAdd(&meaneo[e * DD + t], local);
}

// ---------------- sum / sum^2 of (x - mean(prim)) ----------------
__global__ void uvar_kernel(const float* __restrict__ x, const float* __restrict__ xout5,
                            float* __restrict__ stats)
{
    __shared__ float sm[16];
    const float* a0 = xout5;
    const float* a1 = xout5 + (size_t)NELEM;
    const float* a2 = xout5 + (size_t)2 * NELEM;
    const float* a3 = xout5 + (size_t)3 * NELEM;
    float s1 = 0.f, s2 = 0.f;
    for (size_t i = (size_t)blockIdx.x * blockDim.x + threadIdx.x; i < NELEM;
         i += (size_t)gridDim.x * blockDim.x) {
        float d = x[i] - 0.25f * (a0[i] + a1[i] + a2[i] + a3[i]);
        s1 += d; s2 += d * d;
    }
    s1 = warp_sum(s1); s2 = warp_sum(s2);
    int w = threadIdx.x >> 5;
    if ((threadIdx.x & 31) == 0) { sm[w] = s1; sm[8 + w] = s2; }
    __syncthreads();
    if (threadIdx.x == 0) {
        float a = 0.f, b = 0.f;
        for (int i = 0; i < 8; i++) { a += sm[i]; b += sm[8 + i]; }
        atomicAdd(&stats[0], a);
        atomicAdd(&stats[1], b);
    }
}

// ---------------- gram / ortho / uvar / rate ----------------
__global__ void finalize_kernel(const float* __restrict__ meaneo, float* __restrict__ stats)
{
    __shared__ float sd[16];
    int t = threadIdx.x;  // 256
    if (t < 16) sd[t] = 0.f;
    __syncthreads();
    float l[4][4] = {};
    for (int c = t; c < DD; c += 256) {
        float v[4];
#pragma unroll
        for (int i = 0; i < 4; i++) v[i] = meaneo[i * DD + c];
#pragma unroll
        for (int i = 0; i < 4; i++)
#pragma unroll
            for (int j = i; j < 4; j++) l[i][j] += v[i] * v[j];
    }
#pragma unroll
    for (int i = 0; i < 4; i++)
#pragma unroll
        for (int j = i; j < 4; j++) atomicAdd(&sd[i * 4 + j], l[i][j]);
    __syncthreads();
    if (t == 0) {
        float nrm[4];
        for (int i = 0; i < 4; i++) nrm[i] = sqrtf(sd[i * 4 + i]);
        float off = 0.f;
        for (int i = 0; i < 4; i++)
            for (int j = 0; j < 4; j++) {
                float dot = (i <= j) ? sd[i * 4 + j] : sd[j * 4 + i];
                float gg = dot / (nrm[i] * nrm[j]);
                float dlt = gg - (i == j ? 1.0f : 0.0f);
                off += dlt * dlt;
            }
        float ortho = 1.0f - off / 16.0f;
        float S1 = stats[0], S2 = stats[1];
        const float N = (float)NELEM;
        float uvar = (S2 - S1 * S1 / N) / (N - 1.0f);
        float sat = ortho * uvar;
        stats[2] = (sat > 0.01f) ? 0.01f : 0.0f;
    }
}

// ---------------- combine: (sum_prim + rate * ghost0) / 6 ----------------
__global__ void combine_kernel(const float* __restrict__ xout5,
                               const float* __restrict__ stats, float* __restrict__ out)
{
    float rate = stats[2];
    const float inv6 = 1.0f / 6.0f;
    const float4* a0 = reinterpret_cast<const float4*>(xout5);
    const float4* a1 = reinterpret_cast<const float4*>(xout5 + (size_t)NELEM);
    const float4* a2 = reinterpret_cast<const float4*>(xout5 + (size_t)2 * NELEM);
    const float4* a3 = reinterpret_cast<const float4*>(xout5 + (size_t)3 * NELEM);
    const float4* gh = reinterpret_cast<const float4*>(xout5 + (size_t)4 * NELEM);
    size_t stride = (size_t)gridDim.x * blockDim.x;
    for (size_t i = (size_t)blockIdx.x * blockDim.x + threadIdx.x; i < NELEM / 4; i += stride) {
        float4 s0 = a0[i], s1 = a1[i], s2 = a2[i], s3 = a3[i], g = gh[i];
        float4 o;
        o.x = (s0.x + s1.x + s2.x + s3.x + rate * g.x) * inv6;
        o.y = (s0.y + s1.y + s2.y + s3.y + rate * g.y) * inv6;
        o.z = (s0.z + s1.z + s2.z + s3.z + rate * g.z) * inv6;
        o.w = (s0.w + s1.w + s2.w + s3.w + rate * g.w) * inv6;
        reinterpret_cast<float4*>(out)[i] = o;
    }
}

// ---------------- orchestration ----------------
extern "C" void kernel_launch(void* const* d_in, const int* in_sizes, int n_in,
                              void* d_out, int out_size)
{
    const float* x = (const float*)d_in[0];
    const float* p[12];
    const float* g[12];
    for (int i = 0; i < 12; i++) p[i] = (const float*)d_in[2 + i];
    for (int i = 0; i < 12; i++) g[i] = (const float*)d_in[14 + i];

    float *xn, *qkv, *attno, *x2, *ffh, *xout, *meaneo, *stats;
    float *wqkvt, *wot, *w1t, *w2t;
    cudaGetSymbolAddress((void**)&xn, d_xn);
    cudaGetSymbolAddress((void**)&qkv, d_qkv);
    cudaGetSymbolAddress((void**)&attno, d_attno);
    cudaGetSymbolAddress((void**)&x2, d_x2);
    cudaGetSymbolAddress((void**)&ffh, d_ffh);
    cudaGetSymbolAddress((void**)&xout, d_xout);
    cudaGetSymbolAddress((void**)&meaneo, d_meaneo);
    cudaGetSymbolAddress((void**)&stats, d_stats);
    cudaGetSymbolAddress((void**)&wqkvt, d_wqkvt);
    cudaGetSymbolAddress((void**)&wot, d_wot);
    cudaGetSymbolAddress((void**)&w1t, d_w1t);
    cudaGetSymbolAddress((void**)&w2t, d_w2t);

    const int GEMM_SMEM = STGW * 3 * 4;
    cudaFuncSetAttribute(gemm5<0, true>,  cudaFuncAttributeMaxDynamicSharedMemorySize, GEMM_SMEM);
    cudaFuncSetAttribute(gemm5<1, true>,  cudaFuncAttributeMaxDynamicSharedMemorySize, GEMM_SMEM);
    cudaFuncSetAttribute(gemm5<2, false>, cudaFuncAttributeMaxDynamicSharedMemorySize, GEMM_SMEM);
    cudaFuncSetAttribute(flash_kernel,    cudaFuncAttributeMaxDynamicSharedMemorySize, FLASH_SMEM);

    cudaMemsetAsync(meaneo, 0, 4 * DD * sizeof(float));
    cudaMemsetAsync(stats, 0, 4 * sizeof(float));

    // weights -> tf32, [5][n] layout (4 primary stacked + ghost0)
    roundw_kernel<<<2048, 256>>>(p[2], g[2], wqkvt, (size_t)DD * 3 * DD);
    roundw_kernel<<<2048, 256>>>(p[4], g[4], wot,  (size_t)DD * DD);
    roundw_kernel<<<2048, 256>>>(p[8], g[8], w1t,  (size_t)DD * 4 * DD);
    roundw_kernel<<<2048, 256>>>(p[10], g[10], w2t, (size_t)4 * DD * DD);

    // LN1 (input x shared)
    ln5_kernel<<<dim3(BL, NE), 128>>>(x, 0, 1, p[0], g[0], p[1], g[1], xn);
    // QKV
    gemm5<0, true><<<dim3(12, 32, NE), 256, GEMM_SMEM>>>(
        xn, (size_t)NELEM, wqkvt, (size_t)DD * 3 * DD,
        p[3], g[3], 3 * DD, nullptr, 0, 0, qkv, (size_t)BL * 3 * DD, 3 * DD, DD);
    // flash attention
    flash_kernel<<<dim3(4, 64, NE), 256, FLASH_SMEM>>>(qkv, attno);
    // O projection + residual(x)
    gemm5<2, false><<<dim3(4, 32, NE), 256, GEMM_SMEM>>>(
        attno, (size_t)NELEM, wot, (size_t)DD * DD,
        p[5], g[5], DD, x, 0, 1, x2, (size_t)NELEM, DD, DD);
    // LN2 (input x2 per expert)
    ln5_kernel<<<dim3(BL, NE), 128>>>(x2, (size_t)NELEM, 0, p[6], g[6], p[7], g[7], xn);
    // FFN1 + gelu
    gemm5<1, true><<<dim3(16, 32, NE), 256, GEMM_SMEM>>>(
        xn, (size_t)NELEM, w1t, (size_t)DD * 4 * DD,
        p[9], g[9], 4 * DD, nullptr, 0, 0, ffh, (size_t)BL * 4 * DD, 4 * DD, DD);
    // FFN2 + residual(x2)
    gemm5<2, false><<<dim3(4, 32, NE), 256, GEMM_SMEM>>>(
        ffh, (size_t)BL * 4 * DD, w2t, (size_t)4 * DD * DD,
        p[11], g[11], DD, x2, (size_t)NELEM, 0, xout, (size_t)NELEM, DD, 4 * DD);

    // stats + combine
    meaneo_kernel<<<dim3(32, 4), 512>>>(xout, meaneo);
    uvar_kernel<<<512, 256>>>(x, xout, stats);
    finalize_kernel<<<1, 256>>>(meaneo, stats);
    combine_kernel<<<1024, 256>>>(xout, stats, (float*)d_out);
}

// round 5
// speedup vs baseline: 7.0143x; 1.5347x over previous
#include <cuda_runtime.h>
#include <cuda_bf16.h>
#include <math.h>
#include <stdint.h>

#define BB 8
#define LL 512
#define DD 512
#define HH 8
#define DH 64
#define BL 4096
#define NELEM 2097152
#define NE 5                    // 4 primary + ghost0

// ---------------- scratch (static device globals) ----------------
__device__ __nv_bfloat16 d_xn[(size_t)NE * BL * DD];
__device__ __nv_bfloat16 d_qkv[(size_t)NE * BL * 3 * DD];
__device__ __nv_bfloat16 d_attno[(size_t)NE * BL * DD];
__device__ float         d_x2[(size_t)NE * BL * DD];
__device__ __nv_bfloat16 d_ffh[(size_t)NE * BL * 4 * DD];
__device__ float         d_xout[(size_t)NE * BL * DD];
__device__ __nv_bfloat16 d_wqkvt[(size_t)NE * 3 * DD * DD];  // [N=1536][K=512]
__device__ __nv_bfloat16 d_wot[(size_t)NE * DD * DD];
__device__ __nv_bfloat16 d_w1t[(size_t)NE * 4 * DD * DD];    // [2048][512]
__device__ __nv_bfloat16 d_w2t[(size_t)NE * 4 * DD * DD];    // [512][2048]
__device__ float d_meaneo[4 * DD];
__device__ float d_stats[4];

// ---------------- helpers ----------------
__device__ __forceinline__ float warp_sum(float v) {
#pragma unroll
    for (int o = 16; o > 0; o >>= 1) v += __shfl_xor_sync(0xffffffffu, v, o);
    return v;
}
__device__ __forceinline__ float gelu_tanh(float v) {
    float c = 0.7978845608028654f * (v + 0.044715f * v * v * v);
    return 0.5f * v * (1.0f + tanhf(c));
}
__device__ __forceinline__ uint32_t lh2(const __nv_bfloat16* p) {
    return *reinterpret_cast<const uint32_t*>(p);
}
__device__ __forceinline__ uint32_t packbf(float lo, float hi) {
    __nv_bfloat162 v = __floats2bfloat162_rn(lo, hi);
    return *reinterpret_cast<uint32_t*>(&v);
}
__device__ __forceinline__ void mma16(float* c, const uint32_t* a, const uint32_t* b) {
    asm volatile(
        "mma.sync.aligned.m16n8k16.row.col.f32.bf16.bf16.f32 "
        "{%0,%1,%2,%3},{%4,%5,%6,%7},{%8,%9},{%0,%1,%2,%3};\n"
        : "+f"(c[0]), "+f"(c[1]), "+f"(c[2]), "+f"(c[3])
        : "r"(a[0]), "r"(a[1]), "r"(a[2]), "r"(a[3]), "r"(b[0]), "r"(b[1]));
}
__device__ __forceinline__ void ldsm_x2_trans(uint32_t& r0, uint32_t& r1, const void* p) {
    uint32_t a = (uint32_t)__cvta_generic_to_shared(p);
    asm volatile("ldmatrix.sync.aligned.m8n8.x2.trans.shared.b16 {%0,%1}, [%2];\n"
                 : "=r"(r0), "=r"(r1) : "r"(a));
}
__device__ __forceinline__ void cpa16(void* dst, const void* src) {
    uint32_t d = (uint32_t)__cvta_generic_to_shared(dst);
    asm volatile("cp.async.cg.shared.global [%0], [%1], 16;\n" :: "r"(d), "l"(src));
}
#define CP_COMMIT() asm volatile("cp.async.commit_group;\n" ::: "memory")
#define CP_WAIT1()  asm volatile("cp.async.wait_group 1;\n" ::: "memory")

// ---------------- weight transpose + bf16: [K][N] fp32 -> [N][K] bf16, 5 experts ----------------
__global__ void wtrans_kernel(const float* __restrict__ p, const float* __restrict__ g,
                              __nv_bfloat16* __restrict__ o, int K, int N)
{
    __shared__ float s[32][33];
    int e = blockIdx.z;
    const float* in = (e < 4) ? p + (size_t)e * K * N : g;
    __nv_bfloat16* out = o + (size_t)e * K * N;
    int k0 = blockIdx.x * 32, n0 = blockIdx.y * 32;
    int tx = threadIdx.x, ty = threadIdx.y;   // 32 x 8
#pragma unroll
    for (int r = 0; r < 4; r++)
        s[ty + 8 * r][tx] = in[(size_t)(k0 + ty + 8 * r) * N + n0 + tx];
    __syncthreads();
#pragma unroll
    for (int r = 0; r < 4; r++)
        out[(size_t)(n0 + ty + 8 * r) * K + k0 + tx] = __float2bfloat16_rn(s[tx][ty + 8 * r]);
}

// ---------------- LayerNorm over 5 experts; fp32 in, bf16 out ----------------
__global__ void ln5_kernel(const float* __restrict__ X, size_t sX, int xShared,
                           const float* __restrict__ sP, const float* __restrict__ sG,
                           const float* __restrict__ bP, const float* __restrict__ bG,
                           __nv_bfloat16* __restrict__ Y)
{
    __shared__ float sm[8];
    int e = blockIdx.y;
    const float* x = (xShared ? X : X + (size_t)e * sX) + (size_t)blockIdx.x * DD;
    const float* sc = (e < 4 ? sP + (size_t)e * DD : sG);
    const float* bi = (e < 4 ? bP + (size_t)e * DD : bG);
    __nv_bfloat16* y = Y + (size_t)e * NELEM + (size_t)blockIdx.x * DD;
    int t = threadIdx.x;
    float4 v = reinterpret_cast<const float4*>(x)[t];
    float s = v.x + v.y + v.z + v.w;
    float q = v.x * v.x + v.y * v.y + v.z * v.z + v.w * v.w;
    s = warp_sum(s); q = warp_sum(q);
    if ((t & 31) == 0) { sm[t >> 5] = s; sm[4 + (t >> 5)] = q; }
    __syncthreads();
    float S = sm[0] + sm[1] + sm[2] + sm[3];
    float Q = sm[4] + sm[5] + sm[6] + sm[7];
    float mean = S * (1.0f / DD);
    float var  = Q * (1.0f / DD) - mean * mean;
    float inv  = rsqrtf(var + 1e-5f);
    float4 scv = reinterpret_cast<const float4*>(sc)[t];
    float4 biv = reinterpret_cast<const float4*>(bi)[t];
    uint2 u;
    u.x = packbf((v.x - mean) * inv * scv.x + biv.x, (v.y - mean) * inv * scv.y + biv.y);
    u.y = packbf((v.z - mean) * inv * scv.z + biv.z, (v.w - mean) * inv * scv.w + biv.w);
    *reinterpret_cast<uint2*>(y + 4 * t) = u;
}

// ---------------- bf16 GEMM: 128x128 tiles, BK=32, m16n8k16, cp.async 3-stage, 5-expert z ----
// A [M][K] bf16 row-major; W^T [N][K] bf16. EPI: 0=+bias, 1=+bias+gelu, 2=+bias+res(fp32)
#define AH 40                       // padded halves per smem row
#define STGH (2 * 128 * AH)         // halves per stage (A + B)

template<int EPI, typename OT>
__global__ void __launch_bounds__(256)
gemm5bf(const __nv_bfloat16* __restrict__ Ab, size_t sA,
        const __nv_bfloat16* __restrict__ Wb, size_t sW,
        const float* __restrict__ bP, const float* __restrict__ bG, int sB,
        const float* __restrict__ Rb, size_t sR, int rShared,
        OT* __restrict__ Cb, size_t sC, int N, int K)
{
    extern __shared__ __nv_bfloat16 smh[];
    int e = blockIdx.z;
    const __nv_bfloat16* A = Ab + (size_t)e * sA;
    const __nv_bfloat16* W = Wb + (size_t)e * sW;
    const float* bias = (e < 4 ? bP + (size_t)e * sB : bG);
    const float* R = Rb ? (rShared ? Rb : Rb + (size_t)e * sR) : nullptr;
    OT* C = Cb + (size_t)e * sC;

    int tid = threadIdx.x;
    int lane = tid & 31, warp = tid >> 5;
    int g = lane >> 2, tig = lane & 3;
    int wm = (warp >> 1) * 32, wn = (warp & 1) * 64;
    int bm = blockIdx.y * 128, bn = blockIdx.x * 128;

    float c[2][8][4];
#pragma unroll
    for (int i = 0; i < 2; i++)
#pragma unroll
        for (int j = 0; j < 8; j++)
#pragma unroll
            for (int q = 0; q < 4; q++) c[i][j][q] = 0.f;

    int KT = K >> 5;

#pragma unroll
    for (int s = 0; s < 2; s++) {
        __nv_bfloat16* As = smh + s * STGH;
        __nv_bfloat16* Bs = As + 128 * AH;
        int k0 = s * 32;
#pragma unroll
        for (int i = 0; i < 2; i++) {
            int idx = tid + i * 256;
            int row = idx >> 2, c8 = idx & 3;
            cpa16(As + row * AH + c8 * 8, A + (size_t)(bm + row) * K + k0 + c8 * 8);
            cpa16(Bs + row * AH + c8 * 8, W + (size_t)(bn + row) * K + k0 + c8 * 8);
        }
        CP_COMMIT();
    }

    for (int it = 0; it < KT; it++) {
        CP_WAIT1();
        __syncthreads();
        const __nv_bfloat16* As = smh + (it % 3) * STGH;
        const __nv_bfloat16* Bs = As + 128 * AH;
#pragma unroll
        for (int ks = 0; ks < 2; ks++) {
            int kb = ks * 16;
            uint32_t af[2][4], bf[8][2];
#pragma unroll
            for (int mt = 0; mt < 2; mt++) {
                int mr = wm + mt * 16 + g;
                af[mt][0] = lh2(As + mr * AH + kb + 2 * tig);
                af[mt][1] = lh2(As + (mr + 8) * AH + kb + 2 * tig);
                af[mt][2] = lh2(As + mr * AH + kb + 8 + 2 * tig);
                af[mt][3] = lh2(As + (mr + 8) * AH + kb + 8 + 2 * tig);
            }
#pragma unroll
            for (int nt = 0; nt < 8; nt++) {
                int nc = wn + nt * 8 + g;
                bf[nt][0] = lh2(Bs + nc * AH + kb + 2 * tig);
                bf[nt][1] = lh2(Bs + nc * AH + kb + 8 + 2 * tig);
            }
#pragma unroll
            for (int mt = 0; mt < 2; mt++)
#pragma unroll
                for (int nt = 0; nt < 8; nt++)
                    mma16(c[mt][nt], af[mt], bf[nt]);
        }
        int nx = it + 2;
        if (nx < KT) {
            __nv_bfloat16* Asw = smh + (nx % 3) * STGH;
            __nv_bfloat16* Bsw = Asw + 128 * AH;
            int k0 = nx * 32;
#pragma unroll
            for (int i = 0; i < 2; i++) {
                int idx = tid + i * 256;
                int row = idx >> 2, c8 = idx & 3;
                cpa16(Asw + row * AH + c8 * 8, A + (size_t)(bm + row) * K + k0 + c8 * 8);
                cpa16(Bsw + row * AH + c8 * 8, W + (size_t)(bn + row) * K + k0 + c8 * 8);
            }
        }
        CP_COMMIT();
    }

#pragma unroll
    for (int mt = 0; mt < 2; mt++) {
        int r0 = bm + wm + mt * 16 + g;
        int r1 = r0 + 8;
#pragma unroll
        for (int nt = 0; nt < 8; nt++) {
            int cc = bn + wn + nt * 8 + tig * 2;
            float b0 = bias[cc], b1 = bias[cc + 1];
            float v00 = c[mt][nt][0] + b0, v01 = c[mt][nt][1] + b1;
            float v10 = c[mt][nt][2] + b0, v11 = c[mt][nt][3] + b1;
            if (EPI == 1) {
                v00 = gelu_tanh(v00); v01 = gelu_tanh(v01);
                v10 = gelu_tanh(v10); v11 = gelu_tanh(v11);
            }
            if (EPI == 2) {
                v00 += R[(size_t)r0 * N + cc]; v01 += R[(size_t)r0 * N + cc + 1];
                v10 += R[(size_t)r1 * N + cc]; v11 += R[(size_t)r1 * N + cc + 1];
            }
            if (sizeof(OT) == 2) {
                *reinterpret_cast<uint32_t*>((char*)(C + (size_t)r0 * N + cc)) = packbf(v00, v01);
                *reinterpret_cast<uint32_t*>((char*)(C + (size_t)r1 * N + cc)) = packbf(v10, v11);
            } else {
                *reinterpret_cast<float2*>((char*)(C + (size_t)r0 * N + cc)) = make_float2(v00, v01);
                *reinterpret_cast<float2*>((char*)(C + (size_t)r1 * N + cc)) = make_float2(v10, v11);
            }
        }
    }
}

// ---------------- flash attention bf16: Q-tile 128, j-tiles 64, register-direct P ----------------
// smem halves: Qs[128*72], Ks[64*72], Vs[64*72]
#define FQ 0
#define FK (128 * 72)
#define FV (FK + 64 * 72)
#define FLASH_SMEM ((FV + 64 * 72) * 2)

__global__ void __launch_bounds__(256)
flash_kernel(const __nv_bfloat16* __restrict__ qkv5, __nv_bfloat16* __restrict__ attno5)
{
    extern __shared__ __nv_bfloat16 smh[];
    __nv_bfloat16* Qs = smh + FQ;
    __nv_bfloat16* Ks = smh + FK;
    __nv_bfloat16* Vs = smh + FV;

    int e = blockIdx.z;
    const __nv_bfloat16* qkv = qkv5 + (size_t)e * BL * 3 * DD;
    __nv_bfloat16* attno = attno5 + (size_t)e * NELEM;
    int bh = blockIdx.y;
    int b = bh >> 3, h = bh & 7;
    int i0 = blockIdx.x * 128;
    int tid = threadIdx.x;
    int lane = tid & 31, warp = tid >> 5;
    int g = lane >> 2, tig = lane & 3;
    int wm = warp * 16;

    // stage Q (no scale; 1/8 folded into fp32 S)
#pragma unroll
    for (int i = 0; i < 4; i++) {
        int idx = tid + i * 256;
        int m = idx >> 3, c8 = idx & 7;
        *reinterpret_cast<uint4*>(Qs + m * 72 + c8 * 8) =
            *reinterpret_cast<const uint4*>(qkv + (size_t)(b * LL + i0 + m) * (3 * DD) + h * DH + c8 * 8);
    }

    float o[8][4];
#pragma unroll
    for (int j = 0; j < 8; j++)
#pragma unroll
        for (int q = 0; q < 4; q++) o[j][q] = 0.f;
    float mrow[2] = { -1e30f, -1e30f };
    float lrow[2] = { 0.f, 0.f };

    const __nv_bfloat16* vrow = Vs + (size_t)(lane & 15) * 72;

    for (int jt = 0; jt < 8; jt++) {
        int j0 = jt * 64;
        __syncthreads();
#pragma unroll
        for (int i = 0; i < 2; i++) {
            int idx = tid + i * 256;
            int r = idx >> 3, c8 = idx & 7;
            *reinterpret_cast<uint4*>(Ks + r * 72 + c8 * 8) =
                *reinterpret_cast<const uint4*>(qkv + (size_t)(b * LL + j0 + r) * (3 * DD) + DD + h * DH + c8 * 8);
            *reinterpret_cast<uint4*>(Vs + r * 72 + c8 * 8) =
                *reinterpret_cast<const uint4*>(qkv + (size_t)(b * LL + j0 + r) * (3 * DD) + 2 * DD + h * DH + c8 * 8);
        }
        __syncthreads();

        // S = Q @ K^T  (16x64 per warp), K natural [tok][dh] = B [n][k]
        float c[8][4];
#pragma unroll
        for (int j = 0; j < 8; j++)
#pragma unroll
            for (int q = 0; q < 4; q++) c[j][q] = 0.f;
#pragma unroll
        for (int ks = 0; ks < 4; ks++) {
            int kb = ks * 16;
            uint32_t af[4], bf[8][2];
            int mr = wm + g;
            af[0] = lh2(Qs + mr * 72 + kb + 2 * tig);
            af[1] = lh2(Qs + (mr + 8) * 72 + kb + 2 * tig);
            af[2] = lh2(Qs + mr * 72 + kb + 8 + 2 * tig);
            af[3] = lh2(Qs + (mr + 8) * 72 + kb + 8 + 2 * tig);
#pragma unroll
            for (int nt = 0; nt < 8; nt++) {
                int nc = nt * 8 + g;
                bf[nt][0] = lh2(Ks + nc * 72 + kb + 2 * tig);
                bf[nt][1] = lh2(Ks + nc * 72 + kb + 8 + 2 * tig);
            }
#pragma unroll
            for (int nt = 0; nt < 8; nt++) mma16(c[nt], af, bf[nt]);
        }
#pragma unroll
        for (int nt = 0; nt < 8; nt++)
#pragma unroll
            for (int q = 0; q < 4; q++) c[nt][q] *= 0.125f;

        // online softmax (rows g, g+8; stats across quad)
        float mx0 = -1e30f, mx1 = -1e30f;
#pragma unroll
        for (int nt = 0; nt < 8; nt++) {
            mx0 = fmaxf(mx0, fmaxf(c[nt][0], c[nt][1]));
            mx1 = fmaxf(mx1, fmaxf(c[nt][2], c[nt][3]));
        }
        mx0 = fmaxf(mx0, __shfl_xor_sync(0xffffffffu, mx0, 1));
        mx0 = fmaxf(mx0, __shfl_xor_sync(0xffffffffu, mx0, 2));
        mx1 = fmaxf(mx1, __shfl_xor_sync(0xffffffffu, mx1, 1));
        mx1 = fmaxf(mx1, __shfl_xor_sync(0xffffffffu, mx1, 2));
        float mn0 = fmaxf(mrow[0], mx0), mn1 = fmaxf(mrow[1], mx1);
        float sc0 = __expf(mrow[0] - mn0), sc1 = __expf(mrow[1] - mn1);
        mrow[0] = mn0; mrow[1] = mn1;
        float rs0 = 0.f, rs1 = 0.f;
#pragma unroll
        for (int nt = 0; nt < 8; nt++) {
            c[nt][0] = __expf(c[nt][0] - mn0); c[nt][1] = __expf(c[nt][1] - mn0);
            c[nt][2] = __expf(c[nt][2] - mn1); c[nt][3] = __expf(c[nt][3] - mn1);
            rs0 += c[nt][0] + c[nt][1];
            rs1 += c[nt][2] + c[nt][3];
            o[nt][0] *= sc0; o[nt][1] *= sc0; o[nt][2] *= sc1; o[nt][3] *= sc1;
        }
        rs0 += __shfl_xor_sync(0xffffffffu, rs0, 1);
        rs0 += __shfl_xor_sync(0xffffffffu, rs0, 2);
        rs1 += __shfl_xor_sync(0xffffffffu, rs1, 1);
        rs1 += __shfl_xor_sync(0xffffffffu, rs1, 2);
        lrow[0] = lrow[0] * sc0 + rs0;
        lrow[1] = lrow[1] * sc1 + rs1;

        // O += P @ V ; P register-direct from c, V frags via ldmatrix.trans
#pragma unroll
        for (int ks = 0; ks < 4; ks++) {
            uint32_t af[4];
            af[0] = packbf(c[2 * ks][0],     c[2 * ks][1]);
            af[1] = packbf(c[2 * ks][2],     c[2 * ks][3]);
            af[2] = packbf(c[2 * ks + 1][0], c[2 * ks + 1][1]);
            af[3] = packbf(c[2 * ks + 1][2], c[2 * ks + 1][3]);
            const __nv_bfloat16* vb = vrow + ks * 16 * 72;
#pragma unroll
            for (int nt = 0; nt < 8; nt++) {
                uint32_t b0, b1;
                ldsm_x2_trans(b0, b1, vb + nt * 8);
                uint32_t bfr[2] = { b0, b1 };
                mma16(o[nt], af, bfr);
            }
        }
    }

    float inv0 = __frcp_rn(lrow[0]), inv1 = __frcp_rn(lrow[1]);
    int r0 = i0 + wm + g, r1 = r0 + 8;
#pragma unroll
    for (int nt = 0; nt < 8; nt++) {
        int cc = h * DH + nt * 8 + tig * 2;
        *reinterpret_cast<uint32_t*>(attno + (size_t)(b * LL + r0) * DD + cc) =
            packbf(o[nt][0] * inv0, o[nt][1] * inv0);
        *reinterpret_cast<uint32_t*>(attno + (size_t)(b * LL + r1) * DD + cc) =
            packbf(o[nt][2] * inv1, o[nt][3] * inv1);
    }
}

// ---------------- per-primary-expert column sums ----------------
__global__ void meaneo_kernel(const float* __restrict__ xout5, float* __restrict__ meaneo)
{
    int e = blockIdx.y;
    const float* xo = xout5 + (size_t)e * NELEM;
    int t = threadIdx.x;
    int r0 = blockIdx.x * 128;
    float local = 0.f;
    for (int r = r0; r < r0 + 128; r++) local += xo[(size_t)r * DD + t];
    atomicAdd(&meaneo[e * DD + t], local);
}

// ---------------- sum / sum^2 of (x - mean(prim)) ----------------
__global__ void uvar_kernel(const float* __restrict__ x, const float* __restrict__ xout5,
                            float* __restrict__ stats)
{
    __shared__ float sm[16];
    const float* a0 = xout5;
    const float* a1 = xout5 + (size_t)NELEM;
    const float* a2 = xout5 + (size_t)2 * NELEM;
    const float* a3 = xout5 + (size_t)3 * NELEM;
    float s1 = 0.f, s2 = 0.f;
    for (size_t i = (size_t)blockIdx.x * blockDim.x + threadIdx.x; i < NELEM;
         i += (size_t)gridDim.x * blockDim.x) {
        float d = x[i] - 0.25f * (a0[i] + a1[i] + a2[i] + a3[i]);
        s1 += d; s2 += d * d;
    }
    s1 = warp_sum(s1); s2 = warp_sum(s2);
    int w = threadIdx.x >> 5;
    if ((threadIdx.x & 31) == 0) { sm[w] = s1; sm[8 + w] = s2; }
    __syncthreads();
    if (threadIdx.x == 0) {
        float a = 0.f, b = 0.f;
        for (int i = 0; i < 8; i++) { a += sm[i]; b += sm[8 + i]; }
        atomicAdd(&stats[0], a);
        atomicAdd(&stats[1], b);
    }
}

// ---------------- gram / ortho / uvar / rate ----------------
__global__ void finalize_kernel(const float* __restrict__ meaneo, float* __restrict__ stats)
{
    __shared__ float sd[16];
    int t = threadIdx.x;
    if (t < 16) sd[t] = 0.f;
    __syncthreads();
    float l[4][4] = {};
    for (int c = t; c < DD; c += 256) {
        float v[4];
#pragma unroll
        for (int i = 0; i < 4; i++) v[i] = meaneo[i * DD + c];
#pragma unroll
        for (int i = 0; i < 4; i++)
#pragma unroll
            for (int j = i; j < 4; j++) l[i][j] += v[i] * v[j];
    }
#pragma unroll
    for (int i = 0; i < 4; i++)
#pragma unroll
        for (int j = i; j < 4; j++) atomicAdd(&sd[i * 4 + j], l[i][j]);
    __syncthreads();
    if (t == 0) {
        float nrm[4];
        for (int i = 0; i < 4; i++) nrm[i] = sqrtf(sd[i * 4 + i]);
        float off = 0.f;
        for (int i = 0; i < 4; i++)
            for (int j = 0; j < 4; j++) {
                float dot = (i <= j) ? sd[i * 4 + j] : sd[j * 4 + i];
                float gg = dot / (nrm[i] * nrm[j]);
                float dlt = gg - (i == j ? 1.0f : 0.0f);
                off += dlt * dlt;
            }
        float ortho = 1.0f - off / 16.0f;
        float S1 = stats[0], S2 = stats[1];
        const float N = (float)NELEM;
        float uvar = (S2 - S1 * S1 / N) / (N - 1.0f);
        float sat = ortho * uvar;
        stats[2] = (sat > 0.01f) ? 0.01f : 0.0f;
    }
}

// ---------------- combine: (sum_prim + rate * ghost0) / 6 ----------------
__global__ void combine_kernel(const float* __restrict__ xout5,
                               const float* __restrict__ stats, float* __restrict__ out)
{
    float rate = stats[2];
    const float inv6 = 1.0f / 6.0f;
    const float4* a0 = reinterpret_cast<const float4*>(xout5);
    const float4* a1 = reinterpret_cast<const float4*>(xout5 + (size_t)NELEM);
    const float4* a2 = reinterpret_cast<const float4*>(xout5 + (size_t)2 * NELEM);
    const float4* a3 = reinterpret_cast<const float4*>(xout5 + (size_t)3 * NELEM);
    const float4* gh = reinterpret_cast<const float4*>(xout5 + (size_t)4 * NELEM);
    size_t stride = (size_t)gridDim.x * blockDim.x;
    for (size_t i = (size_t)blockIdx.x * blockDim.x + threadIdx.x; i < NELEM / 4; i += stride) {
        float4 s0 = a0[i], s1 = a1[i], s2 = a2[i], s3 = a3[i], g = gh[i];
        float4 o;
        o.x = (s0.x + s1.x + s2.x + s3.x + rate * g.x) * inv6;
        o.y = (s0.y + s1.y + s2.y + s3.y + rate * g.y) * inv6;
        o.z = (s0.z + s1.z + s2.z + s3.z + rate * g.z) * inv6;
        o.w = (s0.w + s1.w + s2.w + s3.w + rate * g.w) * inv6;
        reinterpret_cast<float4*>(out)[i] = o;
    }
}

// ---------------- orchestration ----------------
extern "C" void kernel_launch(void* const* d_in, const int* in_sizes, int n_in,
                              void* d_out, int out_size)
{
    const float* x = (const float*)d_in[0];
    const float* p[12];
    const float* g[12];
    for (int i = 0; i < 12; i++) p[i] = (const float*)d_in[2 + i];
    for (int i = 0; i < 12; i++) g[i] = (const float*)d_in[14 + i];

    __nv_bfloat16 *xn, *qkv, *attno, *ffh, *wqkvt, *wot, *w1t, *w2t;
    float *x2, *xout, *meaneo, *stats;
    cudaGetSymbolAddress((void**)&xn, d_xn);
    cudaGetSymbolAddress((void**)&qkv, d_qkv);
    cudaGetSymbolAddress((void**)&attno, d_attno);
    cudaGetSymbolAddress((void**)&x2, d_x2);
    cudaGetSymbolAddress((void**)&ffh, d_ffh);
    cudaGetSymbolAddress((void**)&xout, d_xout);
    cudaGetSymbolAddress((void**)&meaneo, d_meaneo);
    cudaGetSymbolAddress((void**)&stats, d_stats);
    cudaGetSymbolAddress((void**)&wqkvt, d_wqkvt);
    cudaGetSymbolAddress((void**)&wot, d_wot);
    cudaGetSymbolAddress((void**)&w1t, d_w1t);
    cudaGetSymbolAddress((void**)&w2t, d_w2t);

    const int GEMM_SMEM = STGH * 3 * 2;     // bytes
    cudaFuncSetAttribute(gemm5bf<0, __nv_bfloat16>, cudaFuncAttributeMaxDynamicSharedMemorySize, GEMM_SMEM);
    cudaFuncSetAttribute(gemm5bf<1, __nv_bfloat16>, cudaFuncAttributeMaxDynamicSharedMemorySize, GEMM_SMEM);
    cudaFuncSetAttribute(gemm5bf<2, float>,         cudaFuncAttributeMaxDynamicSharedMemorySize, GEMM_SMEM);
    cudaFuncSetAttribute(flash_kernel,              cudaFuncAttributeMaxDynamicSharedMemorySize, FLASH_SMEM);

    cudaMemsetAsync(meaneo, 0, 4 * DD * sizeof(float));
    cudaMemsetAsync(stats, 0, 4 * sizeof(float));

    // weights: transpose + bf16, [5][N][K]
    wtrans_kernel<<<dim3(16, 48, NE), dim3(32, 8)>>>(p[2],  g[2],  wqkvt, DD, 3 * DD);
    wtrans_kernel<<<dim3(16, 16, NE), dim3(32, 8)>>>(p[4],  g[4],  wot,   DD, DD);
    wtrans_kernel<<<dim3(16, 64, NE), dim3(32, 8)>>>(p[8],  g[8],  w1t,   DD, 4 * DD);
    wtrans_kernel<<<dim3(64, 16, NE), dim3(32, 8)>>>(p[10], g[10], w2t,   4 * DD, DD);

    // LN1 (x shared)
    ln5_kernel<<<dim3(BL, NE), 128>>>(x, 0, 1, p[0], g[0], p[1], g[1], xn);
    // QKV
    gemm5bf<0, __nv_bfloat16><<<dim3(12, 32, NE), 256, GEMM_SMEM>>>(
        xn, (size_t)NELEM, wqkvt, (size_t)3 * DD * DD,
        p[3], g[3], 3 * DD, nullptr, 0, 0, qkv, (size_t)BL * 3 * DD, 3 * DD, DD);
    // flash attention
    flash_kernel<<<dim3(4, 64, NE), 256, FLASH_SMEM>>>(qkv, attno);
    // O projection + residual(x)
    gemm5bf<2, float><<<dim3(4, 32, NE), 256, GEMM_SMEM>>>(
        attno, (size_t)NELEM, wot, (size_t)DD * DD,
        p[5], g[5], DD, x, 0, 1, x2, (size_t)NELEM, DD, DD);
    // LN2
    ln5_kernel<<<dim3(BL, NE), 128>>>(x2, (size_t)NELEM, 0, p[6], g[6], p[7], g[7], xn);
    // FFN1 + gelu
    gemm5bf<1, __nv_bfloat16><<<dim3(16, 32, NE), 256, GEMM_SMEM>>>(
        xn, (size_t)NELEM, w1t, (size_t)4 * DD * DD,
        p[9], g[9], 4 * DD, nullptr, 0, 0, ffh, (size_t)BL * 4 * DD, 4 * DD, DD);
    // FFN2 + residual(x2)
    gemm5bf<2, float><<<dim3(4, 32, NE), 256, GEMM_SMEM>>>(
        ffh, (size_t)BL * 4 * DD, w2t, (size_t)4 * DD * DD,
        p[11], g[11], DD, x2, (size_t)NELEM, 0, xout, (size_t)NELEM, DD, 4 * DD);

    // stats + combine
    meaneo_kernel<<<dim3(32, 4), 512>>>(xout, meaneo);
    uvar_kernel<<<512, 256>>>(x, xout, stats);
    finalize_kernel<<<1, 256>>>(meaneo, stats);
    combine_kernel<<<1024, 256>>>(xout, stats, (float*)d_out);
}

// round 6
// speedup vs baseline: 7.5483x; 1.0761x over previous
#include <cuda_runtime.h>
#include <cuda_bf16.h>
#include <math.h>
#include <stdint.h>

#define BB 8
#define LL 512
#define DD 512
#define HH 8
#define DH 64
#define BL 4096
#define NELEM 2097152
#define NE 5                    // 4 primary + ghost0

// ---------------- scratch (static device globals) ----------------
__device__ __nv_bfloat16 d_xn[(size_t)NE * BL * DD];
__device__ __nv_bfloat16 d_qkv[(size_t)NE * BL * 3 * DD];
__device__ __nv_bfloat16 d_attno[(size_t)NE * BL * DD];
__device__ float         d_x2[(size_t)NE * BL * DD];
__device__ __nv_bfloat16 d_ffh[(size_t)NE * BL * 4 * DD];
__device__ float         d_xout[(size_t)NE * BL * DD];
__device__ __nv_bfloat16 d_wqkvt[(size_t)NE * 3 * DD * DD];  // [N=1536][K=512]
__device__ __nv_bfloat16 d_wot[(size_t)NE * DD * DD];
__device__ __nv_bfloat16 d_w1t[(size_t)NE * 4 * DD * DD];    // [2048][512]
__device__ __nv_bfloat16 d_w2t[(size_t)NE * 4 * DD * DD];    // [512][2048]
__device__ float d_meaneo[4 * DD];
__device__ float d_stats[4];

// ---------------- helpers ----------------
__device__ __forceinline__ float warp_sum(float v) {
#pragma unroll
    for (int o = 16; o > 0; o >>= 1) v += __shfl_xor_sync(0xffffffffu, v, o);
    return v;
}
__device__ __forceinline__ float gelu_tanh(float v) {
    float c = 0.7978845608028654f * (v + 0.044715f * v * v * v);
    return 0.5f * v * (1.0f + tanhf(c));
}
__device__ __forceinline__ uint32_t packbf(float lo, float hi) {
    __nv_bfloat162 v = __floats2bfloat162_rn(lo, hi);
    return *reinterpret_cast<uint32_t*>(&v);
}
__device__ __forceinline__ void mma16(float* c, const uint32_t* a, const uint32_t* b) {
    asm volatile(
        "mma.sync.aligned.m16n8k16.row.col.f32.bf16.bf16.f32 "
        "{%0,%1,%2,%3},{%4,%5,%6,%7},{%8,%9},{%0,%1,%2,%3};\n"
        : "+f"(c[0]), "+f"(c[1]), "+f"(c[2]), "+f"(c[3])
        : "r"(a[0]), "r"(a[1]), "r"(a[2]), "r"(a[3]), "r"(b[0]), "r"(b[1]));
}
__device__ __forceinline__ void ldsm_x4(uint32_t& r0, uint32_t& r1, uint32_t& r2, uint32_t& r3,
                                        const void* p) {
    uint32_t a = (uint32_t)__cvta_generic_to_shared(p);
    asm volatile("ldmatrix.sync.aligned.m8n8.x4.shared.b16 {%0,%1,%2,%3}, [%4];\n"
                 : "=r"(r0), "=r"(r1), "=r"(r2), "=r"(r3) : "r"(a));
}
__device__ __forceinline__ void ldsm_x2_trans(uint32_t& r0, uint32_t& r1, const void* p) {
    uint32_t a = (uint32_t)__cvta_generic_to_shared(p);
    asm volatile("ldmatrix.sync.aligned.m8n8.x2.trans.shared.b16 {%0,%1}, [%2];\n"
                 : "=r"(r0), "=r"(r1) : "r"(a));
}
__device__ __forceinline__ void cpa16(void* dst, const void* src) {
    uint32_t d = (uint32_t)__cvta_generic_to_shared(dst);
    asm volatile("cp.async.cg.shared.global [%0], [%1], 16;\n" :: "r"(d), "l"(src));
}
#define CP_COMMIT() asm volatile("cp.async.commit_group;\n" ::: "memory")
#define CP_WAIT1()  asm volatile("cp.async.wait_group 1;\n" ::: "memory")

// ---------------- fused weight transpose+bf16 for all 4 weight types, 5 experts --------------
// per-expert tile ranges: [0,768) qkv(512x1536), [768,1024) wo(512x512),
//                         [1024,2048) w1(512x2048), [2048,3072) w2(2048x512)
__global__ void wtrans4_kernel(const float* p0, const float* g0, __nv_bfloat16* o0,
                               const float* p1, const float* g1, __nv_bfloat16* o1,
                               const float* p2, const float* g2, __nv_bfloat16* o2,
                               const float* p3, const float* g3, __nv_bfloat16* o3)
{
    __shared__ float s[32][33];
    int e = blockIdx.y;
    int idx = blockIdx.x;
    const float *p, *g; __nv_bfloat16* o; int K, N;
    if (idx < 768)       { p = p0; g = g0; o = o0; K = 512;  N = 1536; }
    else if (idx < 1024) { p = p1; g = g1; o = o1; K = 512;  N = 512;  idx -= 768; }
    else if (idx < 2048) { p = p2; g = g2; o = o2; K = 512;  N = 2048; idx -= 1024; }
    else                 { p = p3; g = g3; o = o3; K = 2048; N = 512;  idx -= 2048; }
    int tkx = K >> 5;
    int k0 = (idx % tkx) * 32, n0 = (idx / tkx) * 32;
    const float* in = (e < 4) ? p + (size_t)e * K * N : g;
    __nv_bfloat16* out = o + (size_t)e * K * N;
    int tx = threadIdx.x, ty = threadIdx.y;   // 32 x 8
#pragma unroll
    for (int r = 0; r < 4; r++)
        s[ty + 8 * r][tx] = in[(size_t)(k0 + ty + 8 * r) * N + n0 + tx];
    __syncthreads();
#pragma unroll
    for (int r = 0; r < 4; r++)
        out[(size_t)(n0 + ty + 8 * r) * K + k0 + tx] = __float2bfloat16_rn(s[tx][ty + 8 * r]);
}

// ---------------- LayerNorm over 5 experts; fp32 in, bf16 out ----------------
__global__ void ln5_kernel(const float* __restrict__ X, size_t sX, int xShared,
                           const float* __restrict__ sP, const float* __restrict__ sG,
                           const float* __restrict__ bP, const float* __restrict__ bG,
                           __nv_bfloat16* __restrict__ Y)
{
    __shared__ float sm[8];
    int e = blockIdx.y;
    const float* x = (xShared ? X : X + (size_t)e * sX) + (size_t)blockIdx.x * DD;
    const float* sc = (e < 4 ? sP + (size_t)e * DD : sG);
    const float* bi = (e < 4 ? bP + (size_t)e * DD : bG);
    __nv_bfloat16* y = Y + (size_t)e * NELEM + (size_t)blockIdx.x * DD;
    int t = threadIdx.x;
    float4 v = reinterpret_cast<const float4*>(x)[t];
    float s = v.x + v.y + v.z + v.w;
    float q = v.x * v.x + v.y * v.y + v.z * v.z + v.w * v.w;
    s = warp_sum(s); q = warp_sum(q);
    if ((t & 31) == 0) { sm[t >> 5] = s; sm[4 + (t >> 5)] = q; }
    __syncthreads();
    float S = sm[0] + sm[1] + sm[2] + sm[3];
    float Q = sm[4] + sm[5] + sm[6] + sm[7];
    float mean = S * (1.0f / DD);
    float var  = Q * (1.0f / DD) - mean * mean;
    float inv  = rsqrtf(var + 1e-5f);
    float4 scv = reinterpret_cast<const float4*>(sc)[t];
    float4 biv = reinterpret_cast<const float4*>(bi)[t];
    uint2 u;
    u.x = packbf((v.x - mean) * inv * scv.x + biv.x, (v.y - mean) * inv * scv.y + biv.y);
    u.y = packbf((v.z - mean) * inv * scv.z + biv.z, (v.w - mean) * inv * scv.w + biv.w);
    *reinterpret_cast<uint2*>(y + 4 * t) = u;
}

// ---------------- bf16 GEMM: 128x128 tiles, BK=32, ldmatrix fragments ----------------
#define AH 40
#define STGH (2 * 128 * AH)

template<int EPI, typename OT>
__global__ void __launch_bounds__(256)
gemm5bf(const __nv_bfloat16* __restrict__ Ab, size_t sA,
        const __nv_bfloat16* __restrict__ Wb, size_t sW,
        const float* __restrict__ bP, const float* __restrict__ bG, int sB,
        const float* __restrict__ Rb, size_t sR, int rShared,
        OT* __restrict__ Cb, size_t sC, int N, int K)
{
    extern __shared__ __nv_bfloat16 smh[];
    int e = blockIdx.z;
    const __nv_bfloat16* A = Ab + (size_t)e * sA;
    const __nv_bfloat16* W = Wb + (size_t)e * sW;
    const float* bias = (e < 4 ? bP + (size_t)e * sB : bG);
    const float* R = Rb ? (rShared ? Rb : Rb + (size_t)e * sR) : nullptr;
    OT* C = Cb + (size_t)e * sC;

    int tid = threadIdx.x;
    int lane = tid & 31, warp = tid >> 5;
    int g = lane >> 2, tig = lane & 3;
    int lr = lane & 7, sel = lane >> 3;     // ldmatrix address decomposition
    int wm = (warp >> 1) * 32, wn = (warp & 1) * 64;
    int bm = blockIdx.y * 128, bn = blockIdx.x * 128;

    float c[2][8][4];
#pragma unroll
    for (int i = 0; i < 2; i++)
#pragma unroll
        for (int j = 0; j < 8; j++)
#pragma unroll
            for (int q = 0; q < 4; q++) c[i][j][q] = 0.f;

    int KT = K >> 5;

#pragma unroll
    for (int s = 0; s < 2; s++) {
        __nv_bfloat16* As = smh + s * STGH;
        __nv_bfloat16* Bs = As + 128 * AH;
        int k0 = s * 32;
#pragma unroll
        for (int i = 0; i < 2; i++) {
            int idx = tid + i * 256;
            int row = idx >> 2, c8 = idx & 3;
            cpa16(As + row * AH + c8 * 8, A + (size_t)(bm + row) * K + k0 + c8 * 8);
            cpa16(Bs + row * AH + c8 * 8, W + (size_t)(bn + row) * K + k0 + c8 * 8);
        }
        CP_COMMIT();
    }

    for (int it = 0; it < KT; it++) {
        CP_WAIT1();
        __syncthreads();
        const __nv_bfloat16* As = smh + (it % 3) * STGH;
        const __nv_bfloat16* Bs = As + 128 * AH;
#pragma unroll
        for (int ks = 0; ks < 2; ks++) {
            int kb = ks * 16;
            uint32_t af[2][4], bf[8][2];
#pragma unroll
            for (int mt = 0; mt < 2; mt++) {
                const __nv_bfloat16* pa =
                    As + (size_t)(wm + mt * 16 + lr + (sel & 1) * 8) * AH + kb + (sel >> 1) * 8;
                ldsm_x4(af[mt][0], af[mt][1], af[mt][2], af[mt][3], pa);
            }
#pragma unroll
            for (int nt2 = 0; nt2 < 4; nt2++) {
                const __nv_bfloat16* pb =
                    Bs + (size_t)(wn + nt2 * 16 + lr + (sel >> 1) * 8) * AH + kb + (sel & 1) * 8;
                ldsm_x4(bf[2 * nt2][0], bf[2 * nt2][1], bf[2 * nt2 + 1][0], bf[2 * nt2 + 1][1], pb);
            }
#pragma unroll
            for (int mt = 0; mt < 2; mt++)
#pragma unroll
                for (int nt = 0; nt < 8; nt++)
                    mma16(c[mt][nt], af[mt], bf[nt]);
        }
        int nx = it + 2;
        if (nx < KT) {
            __nv_bfloat16* Asw = smh + (nx % 3) * STGH;
            __nv_bfloat16* Bsw = Asw + 128 * AH;
            int k0 = nx * 32;
#pragma unroll
            for (int i = 0; i < 2; i++) {
                int idx = tid + i * 256;
                int row = idx >> 2, c8 = idx & 3;
                cpa16(Asw + row * AH + c8 * 8, A + (size_t)(bm + row) * K + k0 + c8 * 8);
                cpa16(Bsw + row * AH + c8 * 8, W + (size_t)(bn + row) * K + k0 + c8 * 8);
            }
        }
        CP_COMMIT();
    }

#pragma unroll
    for (int mt = 0; mt < 2; mt++) {
        int r0 = bm + wm + mt * 16 + g;
        int r1 = r0 + 8;
#pragma unroll
        for (int nt = 0; nt < 8; nt++) {
            int cc = bn + wn + nt * 8 + tig * 2;
            float b0 = bias[cc], b1 = bias[cc + 1];
            float v00 = c[mt][nt][0] + b0, v01 = c[mt][nt][1] + b1;
            float v10 = c[mt][nt][2] + b0, v11 = c[mt][nt][3] + b1;
            if (EPI == 1) {
                v00 = gelu_tanh(v00); v01 = gelu_tanh(v01);
                v10 = gelu_tanh(v10); v11 = gelu_tanh(v11);
            }
            if (EPI == 2) {
                v00 += R[(size_t)r0 * N + cc]; v01 += R[(size_t)r0 * N + cc + 1];
                v10 += R[(size_t)r1 * N + cc]; v11 += R[(size_t)r1 * N + cc + 1];
            }
            if (sizeof(OT) == 2) {
                *reinterpret_cast<uint32_t*>((char*)(C + (size_t)r0 * N + cc)) = packbf(v00, v01);
                *reinterpret_cast<uint32_t*>((char*)(C + (size_t)r1 * N + cc)) = packbf(v10, v11);
            } else {
                *reinterpret_cast<float2*>((char*)(C + (size_t)r0 * N + cc)) = make_float2(v00, v01);
                *reinterpret_cast<float2*>((char*)(C + (size_t)r1 * N + cc)) = make_float2(v10, v11);
            }
        }
    }
}

// ---------------- flash attention bf16 with ldmatrix fragments ----------------
#define FQ 0
#define FK (128 * 72)
#define FV (FK + 64 * 72)
#define FLASH_SMEM ((FV + 64 * 72) * 2)

__global__ void __launch_bounds__(256)
flash_kernel(const __nv_bfloat16* __restrict__ qkv5, __nv_bfloat16* __restrict__ attno5)
{
    extern __shared__ __nv_bfloat16 smh[];
    __nv_bfloat16* Qs = smh + FQ;
    __nv_bfloat16* Ks = smh + FK;
    __nv_bfloat16* Vs = smh + FV;

    int e = blockIdx.z;
    const __nv_bfloat16* qkv = qkv5 + (size_t)e * BL * 3 * DD;
    __nv_bfloat16* attno = attno5 + (size_t)e * NELEM;
    int bh = blockIdx.y;
    int b = bh >> 3, h = bh & 7;
    int i0 = blockIdx.x * 128;
    int tid = threadIdx.x;
    int lane = tid & 31, warp = tid >> 5;
    int g = lane >> 2, tig = lane & 3;
    int lr = lane & 7, sel = lane >> 3;
    int wm = warp * 16;

#pragma unroll
    for (int i = 0; i < 4; i++) {
        int idx = tid + i * 256;
        int m = idx >> 3, c8 = idx & 7;
        *reinterpret_cast<uint4*>(Qs + m * 72 + c8 * 8) =
            *reinterpret_cast<const uint4*>(qkv + (size_t)(b * LL + i0 + m) * (3 * DD) + h * DH + c8 * 8);
    }

    float o[8][4];
#pragma unroll
    for (int j = 0; j < 8; j++)
#pragma unroll
        for (int q = 0; q < 4; q++) o[j][q] = 0.f;
    float mrow[2] = { -1e30f, -1e30f };
    float lrow[2] = { 0.f, 0.f };

    const __nv_bfloat16* vrow = Vs + (size_t)(lane & 15) * 72;

    for (int jt = 0; jt < 8; jt++) {
        int j0 = jt * 64;
        __syncthreads();
#pragma unroll
        for (int i = 0; i < 2; i++) {
            int idx = tid + i * 256;
            int r = idx >> 3, c8 = idx & 7;
            *reinterpret_cast<uint4*>(Ks + r * 72 + c8 * 8) =
                *reinterpret_cast<const uint4*>(qkv + (size_t)(b * LL + j0 + r) * (3 * DD) + DD + h * DH + c8 * 8);
            *reinterpret_cast<uint4*>(Vs + r * 72 + c8 * 8) =
                *reinterpret_cast<const uint4*>(qkv + (size_t)(b * LL + j0 + r) * (3 * DD) + 2 * DD + h * DH + c8 * 8);
        }
        __syncthreads();

        // S = Q @ K^T (16x64 per warp)
        float c[8][4];
#pragma unroll
        for (int j = 0; j < 8; j++)
#pragma unroll
            for (int q = 0; q < 4; q++) c[j][q] = 0.f;
#pragma unroll
        for (int ks = 0; ks < 4; ks++) {
            int kb = ks * 16;
            uint32_t af[4], bf[8][2];
            const __nv_bfloat16* pa =
                Qs + (size_t)(wm + lr + (sel & 1) * 8) * 72 + kb + (sel >> 1) * 8;
            ldsm_x4(af[0], af[1], af[2], af[3], pa);
#pragma unroll
            for (int nt2 = 0; nt2 < 4; nt2++) {
                const __nv_bfloat16* pb =
                    Ks + (size_t)(nt2 * 16 + lr + (sel >> 1) * 8) * 72 + kb + (sel & 1) * 8;
                ldsm_x4(bf[2 * nt2][0], bf[2 * nt2][1], bf[2 * nt2 + 1][0], bf[2 * nt2 + 1][1], pb);
            }
#pragma unroll
            for (int nt = 0; nt < 8; nt++) mma16(c[nt], af, bf[nt]);
        }
#pragma unroll
        for (int nt = 0; nt < 8; nt++)
#pragma unroll
            for (int q = 0; q < 4; q++) c[nt][q] *= 0.125f;

        // online softmax
        float mx0 = -1e30f, mx1 = -1e30f;
#pragma unroll
        for (int nt = 0; nt < 8; nt++) {
            mx0 = fmaxf(mx0, fmaxf(c[nt][0], c[nt][1]));
            mx1 = fmaxf(mx1, fmaxf(c[nt][2], c[nt][3]));
        }
        mx0 = fmaxf(mx0, __shfl_xor_sync(0xffffffffu, mx0, 1));
        mx0 = fmaxf(mx0, __shfl_xor_sync(0xffffffffu, mx0, 2));
        mx1 = fmaxf(mx1, __shfl_xor_sync(0xffffffffu, mx1, 1));
        mx1 = fmaxf(mx1, __shfl_xor_sync(0xffffffffu, mx1, 2));
        float mn0 = fmaxf(mrow[0], mx0), mn1 = fmaxf(mrow[1], mx1);
        float sc0 = __expf(mrow[0] - mn0), sc1 = __expf(mrow[1] - mn1);
        mrow[0] = mn0; mrow[1] = mn1;
        float rs0 = 0.f, rs1 = 0.f;
#pragma unroll
        for (int nt = 0; nt < 8; nt++) {
            c[nt][0] = __expf(c[nt][0] - mn0); c[nt][1] = __expf(c[nt][1] - mn0);
            c[nt][2] = __expf(c[nt][2] - mn1); c[nt][3] = __expf(c[nt][3] - mn1);
            rs0 += c[nt][0] + c[nt][1];
            rs1 += c[nt][2] + c[nt][3];
            o[nt][0] *= sc0; o[nt][1] *= sc0; o[nt][2] *= sc1; o[nt][3] *= sc1;
        }
        rs0 += __shfl_xor_sync(0xffffffffu, rs0, 1);
        rs0 += __shfl_xor_sync(0xffffffffu, rs0, 2);
        rs1 += __shfl_xor_sync(0xffffffffu, rs1, 1);
        rs1 += __shfl_xor_sync(0xffffffffu, rs1, 2);
        lrow[0] = lrow[0] * sc0 + rs0;
        lrow[1] = lrow[1] * sc1 + rs1;

        // O += P @ V ; P register-direct, V via ldmatrix.trans
#pragma unroll
        for (int ks = 0; ks < 4; ks++) {
            uint32_t af[4];
            af[0] = packbf(c[2 * ks][0],     c[2 * ks][1]);
            af[1] = packbf(c[2 * ks][2],     c[2 * ks][3]);
            af[2] = packbf(c[2 * ks + 1][0], c[2 * ks + 1][1]);
            af[3] = packbf(c[2 * ks + 1][2], c[2 * ks + 1][3]);
            const __nv_bfloat16* vb = vrow + ks * 16 * 72;
#pragma unroll
            for (int nt = 0; nt < 8; nt++) {
                uint32_t b0, b1;
                ldsm_x2_trans(b0, b1, vb + nt * 8);
                uint32_t bfr[2] = { b0, b1 };
                mma16(o[nt], af, bfr);
            }
        }
    }

    float inv0 = __frcp_rn(lrow[0]), inv1 = __frcp_rn(lrow[1]);
    int r0 = i0 + wm + g, r1 = r0 + 8;
#pragma unroll
    for (int nt = 0; nt < 8; nt++) {
        int cc = h * DH + nt * 8 + tig * 2;
        *reinterpret_cast<uint32_t*>(attno + (size_t)(b * LL + r0) * DD + cc) =
            packbf(o[nt][0] * inv0, o[nt][1] * inv0);
        *reinterpret_cast<uint32_t*>(attno + (size_t)(b * LL + r1) * DD + cc) =
            packbf(o[nt][2] * inv1, o[nt][3] * inv1);
    }
}

// ---------------- per-primary-expert column sums ----------------
__global__ void meaneo_kernel(const float* __restrict__ xout5, float* __restrict__ meaneo)
{
    int e = blockIdx.y;
    const float* xo = xout5 + (size_t)e * NELEM;
    int t = threadIdx.x;
    int r0 = blockIdx.x * 128;
    float local = 0.f;
    for (int r = r0; r < r0 + 128; r++) local += xo[(size_t)r * DD + t];
    atomicAdd(&meaneo[e * DD + t], local);
}

// ---------------- sum / sum^2 of (x - mean(prim)) ----------------
__global__ void uvar_kernel(const float* __restrict__ x, const float* __restrict__ xout5,
                            float* __restrict__ stats)
{
    __shared__ float sm[16];
    const float* a0 = xout5;
    const float* a1 = xout5 + (size_t)NELEM;
    const float* a2 = xout5 + (size_t)2 * NELEM;
    const float* a3 = xout5 + (size_t)3 * NELEM;
    float s1 = 0.f, s2 = 0.f;
    for (size_t i = (size_t)blockIdx.x * blockDim.x + threadIdx.x; i < NELEM;
         i += (size_t)gridDim.x * blockDim.x) {
        float d = x[i] - 0.25f * (a0[i] + a1[i] + a2[i] + a3[i]);
        s1 += d; s2 += d * d;
    }
    s1 = warp_sum(s1); s2 = warp_sum(s2);
    int w = threadIdx.x >> 5;
    if ((threadIdx.x & 31) == 0) { sm[w] = s1; sm[8 + w] = s2; }
    __syncthreads();
    if (threadIdx.x == 0) {
        float a = 0.f, b = 0.f;
        for (int i = 0; i < 8; i++) { a += sm[i]; b += sm[8 + i]; }
        atomicAdd(&stats[0], a);
        atomicAdd(&stats[1], b);
    }
}

// ---------------- gram / ortho / uvar / rate ----------------
__global__ void finalize_kernel(const float* __restrict__ meaneo, float* __restrict__ stats)
{
    __shared__ float sd[16];
    int t = threadIdx.x;
    if (t < 16) sd[t] = 0.f;
    __syncthreads();
    float l[4][4] = {};
    for (int c = t; c < DD; c += 256) {
        float v[4];
#pragma unroll
        for (int i = 0; i < 4; i++) v[i] = meaneo[i * DD + c];
#pragma unroll
        for (int i = 0; i < 4; i++)
#pragma unroll
            for (int j = i; j < 4; j++) l[i][j] += v[i] * v[j];
    }
#pragma unroll
    for (int i = 0; i < 4; i++)
#pragma unroll
        for (int j = i; j < 4; j++) atomicAdd(&sd[i * 4 + j], l[i][j]);
    __syncthreads();
    if (t == 0) {
        float nrm[4];
        for (int i = 0; i < 4; i++) nrm[i] = sqrtf(sd[i * 4 + i]);
        float off = 0.f;
        for (int i = 0; i < 4; i++)
            for (int j = 0; j < 4; j++) {
                float dot = (i <= j) ? sd[i * 4 + j] : sd[j * 4 + i];
                float gg = dot / (nrm[i] * nrm[j]);
                float dlt = gg - (i == j ? 1.0f : 0.0f);
                off += dlt * dlt;
            }
        float ortho = 1.0f - off / 16.0f;
        float S1 = stats[0], S2 = stats[1];
        const float N = (float)NELEM;
        float uvar = (S2 - S1 * S1 / N) / (N - 1.0f);
        float sat = ortho * uvar;
        stats[2] = (sat > 0.01f) ? 0.01f : 0.0f;
    }
}

// ---------------- combine: (sum_prim + rate * ghost0) / 6 ----------------
__global__ void combine_kernel(const float* __restrict__ xout5,
                               const float* __restrict__ stats, float* __restrict__ out)
{
    float rate = stats[2];
    const float inv6 = 1.0f / 6.0f;
    const float4* a0 = reinterpret_cast<const float4*>(xout5);
    const float4* a1 = reinterpret_cast<const float4*>(xout5 + (size_t)NELEM);
    const float4* a2 = reinterpret_cast<const float4*>(xout5 + (size_t)2 * NELEM);
    const float4* a3 = reinterpret_cast<const float4*>(xout5 + (size_t)3 * NELEM);
    const float4* gh = reinterpret_cast<const float4*>(xout5 + (size_t)4 * NELEM);
    size_t stride = (size_t)gridDim.x * blockDim.x;
    for (size_t i = (size_t)blockIdx.x * blockDim.x + threadIdx.x; i < NELEM / 4; i += stride) {
        float4 s0 = a0[i], s1 = a1[i], s2 = a2[i], s3 = a3[i], g = gh[i];
        float4 o;
        o.x = (s0.x + s1.x + s2.x + s3.x + rate * g.x) * inv6;
        o.y = (s0.y + s1.y + s2.y + s3.y + rate * g.y) * inv6;
        o.z = (s0.z + s1.z + s2.z + s3.z + rate * g.z) * inv6;
        o.w = (s0.w + s1.w + s2.w + s3.w + rate * g.w) * inv6;
        reinterpret_cast<float4*>(out)[i] = o;
    }
}

// ---------------- orchestration ----------------
extern "C" void kernel_launch(void* const* d_in, const int* in_sizes, int n_in,
                              void* d_out, int out_size)
{
    const float* x = (const float*)d_in[0];
    const float* p[12];
    const float* g[12];
    for (int i = 0; i < 12; i++) p[i] = (const float*)d_in[2 + i];
    for (int i = 0; i < 12; i++) g[i] = (const float*)d_in[14 + i];

    __nv_bfloat16 *xn, *qkv, *attno, *ffh, *wqkvt, *wot, *w1t, *w2t;
    float *x2, *xout, *meaneo, *stats;
    cudaGetSymbolAddress((void**)&xn, d_xn);
    cudaGetSymbolAddress((void**)&qkv, d_qkv);
    cudaGetSymbolAddress((void**)&attno, d_attno);
    cudaGetSymbolAddress((void**)&x2, d_x2);
    cudaGetSymbolAddress((void**)&ffh, d_ffh);
    cudaGetSymbolAddress((void**)&xout, d_xout);
    cudaGetSymbolAddress((void**)&meaneo, d_meaneo);
    cudaGetSymbolAddress((void**)&stats, d_stats);
    cudaGetSymbolAddress((void**)&wqkvt, d_wqkvt);
    cudaGetSymbolAddress((void**)&wot, d_wot);
    cudaGetSymbolAddress((void**)&w1t, d_w1t);
    cudaGetSymbolAddress((void**)&w2t, d_w2t);

    const int GEMM_SMEM = STGH * 3 * 2;
    cudaFuncSetAttribute(gemm5bf<0, __nv_bfloat16>, cudaFuncAttributeMaxDynamicSharedMemorySize, GEMM_SMEM);
    cudaFuncSetAttribute(gemm5bf<1, __nv_bfloat16>, cudaFuncAttributeMaxDynamicSharedMemorySize, GEMM_SMEM);
    cudaFuncSetAttribute(gemm5bf<2, float>,         cudaFuncAttributeMaxDynamicSharedMemorySize, GEMM_SMEM);
    cudaFuncSetAttribute(flash_kernel,              cudaFuncAttributeMaxDynamicSharedMemorySize, FLASH_SMEM);

    cudaMemsetAsync(meaneo, 0, 4 * DD * sizeof(float));
    cudaMemsetAsync(stats, 0, 4 * sizeof(float));

    // fused weight transpose+bf16 (all 4 weight types, 5 experts, one launch)
    wtrans4_kernel<<<dim3(3072, NE), dim3(32, 8)>>>(
        p[2], g[2], wqkvt, p[4], g[4], wot, p[8], g[8], w1t, p[10], g[10], w2t);

    // LN1 (x shared)
    ln5_kernel<<<dim3(BL, NE), 128>>>(x, 0, 1, p[0], g[0], p[1], g[1], xn);
    // QKV
    gemm5bf<0, __nv_bfloat16><<<dim3(12, 32, NE), 256, GEMM_SMEM>>>(
        xn, (size_t)NELEM, wqkvt, (size_t)3 * DD * DD,
        p[3], g[3], 3 * DD, nullptr, 0, 0, qkv, (size_t)BL * 3 * DD, 3 * DD, DD);
    // flash attention
    flash_kernel<<<dim3(4, 64, NE), 256, FLASH_SMEM>>>(qkv, attno);
    // O projection + residual(x)
    gemm5bf<2, float><<<dim3(4, 32, NE), 256, GEMM_SMEM>>>(
        attno, (size_t)NELEM, wot, (size_t)DD * DD,
        p[5], g[5], DD, x, 0, 1, x2, (size_t)NELEM, DD, DD);
    // LN2
    ln5_kernel<<<dim3(BL, NE), 128>>>(x2, (size_t)NELEM, 0, p[6], g[6], p[7], g[7], xn);
    // FFN1 + gelu
    gemm5bf<1, __nv_bfloat16><<<dim3(16, 32, NE), 256, GEMM_SMEM>>>(
        xn, (size_t)NELEM, w1t, (size_t)4 * DD * DD,
        p[9], g[9], 4 * DD, nullptr, 0, 0, ffh, (size_t)BL * 4 * DD, 4 * DD, DD);
    // FFN2 + residual(x2)
    gemm5bf<2, float><<<dim3(4, 32, NE), 256, GEMM_SMEM>>>(
        ffh, (size_t)BL * 4 * DD, w2t, (size_t)4 * DD * DD,
        p[11], g[11], DD, x2, (size_t)NELEM, 0, xout, (size_t)NELEM, DD, 4 * DD);

    // stats + combine
    meaneo_kernel<<<dim3(32, 4), 512>>>(xout, meaneo);
    uvar_kernel<<<512, 256>>>(x, xout, stats);
    finalize_kernel<<<1, 256>>>(meaneo, stats);
    combine_kernel<<<1024, 256>>>(xout, stats, (float*)d_out);
}